// round 8
// baseline (speedup 1.0000x reference)
#include <cuda_runtime.h>
#include <cuda_bf16.h>
#include <cstdint>

#define DI __device__ __forceinline__
#define FULLMASK 0xFFFFFFFFu

// ===================== problem dims =====================
#define NBATCH 4
#define NPIX   4096
#define NCH    1792
#define NCENT  4096
#define M_TOT  (NBATCH*NPIX)
#define NNEI   200
#define SCORE_ELEMS (NBATCH*NNEI*NPIX)

// ===================== scratch =====================
__device__ float g_pool0[4u*256*64*64];
__device__ float g_pool1[4u*512*32*32];
__device__ float g_pool2[4u*1024*16*16];
__device__ float g_conv0[4u*256*64*64];
__device__ float g_conv1[4u*512*32*32];
__device__ float g_conv2[4u*1024*16*16];
__device__ __nv_bfloat16 g_phi[(size_t)M_TOT*NCH];
__device__ __nv_bfloat16 g_ct [(size_t)NCENT*NCH];
__device__ float g_feats[M_TOT];
__device__ float g_cents[NCENT];
__device__ float g_dist2[(size_t)M_TOT*NCENT];

// ===================== PTX helpers (sm_100 baseline ISA) =====================
DI uint32_t smem_u32(const void* p) {
    uint32_t a;
    asm("{ .reg .u64 t; cvta.to.shared.u64 t, %1; cvt.u32.u64 %0, t; }" : "=r"(a) : "l"(p));
    return a;
}
DI void ldsm4(uint32_t* r, uint32_t a) {
    asm volatile("ldmatrix.sync.aligned.m8n8.x4.shared.b16 {%0,%1,%2,%3}, [%4];"
        : "=r"(r[0]), "=r"(r[1]), "=r"(r[2]), "=r"(r[3]) : "r"(a));
}
DI void mma16816(float* c, const uint32_t* a, uint32_t b0, uint32_t b1) {
    asm volatile("mma.sync.aligned.m16n8k16.row.col.f32.bf16.bf16.f32 "
        "{%0,%1,%2,%3}, {%4,%5,%6,%7}, {%8,%9}, {%0,%1,%2,%3};"
        : "+f"(c[0]), "+f"(c[1]), "+f"(c[2]), "+f"(c[3])
        : "r"(a[0]), "r"(a[1]), "r"(a[2]), "r"(a[3]), "r"(b0), "r"(b1));
}
DI void cpasync16(uint32_t dst, const void* src) {
    asm volatile("cp.async.cg.shared.global [%0], [%1], 16;" :: "r"(dst), "l"(src) : "memory");
}
DI void cp_commit() { asm volatile("cp.async.commit_group;" ::: "memory"); }
DI void cp_wait2()  { asm volatile("cp.async.wait_group 2;" ::: "memory"); }
DI void cp_wait1()  { asm volatile("cp.async.wait_group 1;" ::: "memory"); }
DI void cp_wait0()  { asm volatile("cp.async.wait_group 0;" ::: "memory"); }

// ===================== launch 1: prep mega-kernel =====================
DI void pool_body(const float* __restrict__ x, float* __restrict__ y,
                  int H, int W, int idx) {
    int w = idx % W;
    int h = (idx / W) % H;
    int bc = idx / (W * H);
    const float* p = x + (size_t)bc * H * W;
    float s = 0.f;
    #pragma unroll
    for (int dy = -1; dy <= 1; dy++) {
        int hh = h + dy;
        if (hh < 0 || hh >= H) continue;
        #pragma unroll
        for (int dx = -1; dx <= 1; dx++) {
            int ww = w + dx;
            if (ww < 0 || ww >= W) continue;
            s += p[hh * W + ww];
        }
    }
    y[idx] = s * (1.0f / 9.0f);
}

__global__ __launch_bounds__(256) void prep_kernel(
    const float* __restrict__ p0, const float* __restrict__ p1,
    const float* __restrict__ p2, const float* __restrict__ C) {
    int bb = blockIdx.x, t = threadIdx.x;
    if (bb < 16384) {
        pool_body(p0, g_pool0, 64, 64, bb * 256 + t);
    } else if (bb < 24576) {
        pool_body(p1, g_pool1, 32, 32, (bb - 16384) * 256 + t);
    } else if (bb < 28672) {
        pool_body(p2, g_pool2, 16, 16, (bb - 24576) * 256 + t);
    } else if (bb < 35840) {
        __shared__ float tile[32][33];
        int id = bb - 28672;
        int j0 = (id & 127) * 32, k0 = (id >> 7) * 32;
        int tx = t & 31, ty = t >> 5;
        for (int i = ty; i < 32; i += 8)
            tile[i][tx] = C[(size_t)(k0 + i) * 4096 + j0 + tx];
        __syncthreads();
        for (int i = ty; i < 32; i += 8)
            g_ct[(size_t)(j0 + i) * NCH + k0 + tx] = __float2bfloat16(tile[tx][i]);
    } else if (bb < 35968) {
        __shared__ float red[256];
        int id = bb - 35840;
        int j = (id & 127) * 32 + (t & 31);
        int kp = t >> 5;
        float s = 0.f;
        int kbeg = kp * 224, kend = kbeg + 224;
        for (int k = kbeg; k < kend; k++) {
            float v = C[(size_t)k * 4096 + j];
            s += v * v;
        }
        red[t] = s;
        __syncthreads();
        if (t < 32) {
            float acc = red[t];
            #pragma unroll
            for (int i = 1; i < 8; i++) acc += red[t + i * 32];
            g_cents[j] = acc;
        }
    } else {
        g_feats[(bb - 35968) * 256 + t] = 0.f;
    }
}

// ===================== launch 2: coord-conv (128oc x 64px tile, 8x4/thread) =====================
DI void conv_body(const float* __restrict__ x, const float* __restrict__ w,
                  const float* __restrict__ bias, float* __restrict__ o,
                  int C, int OC, int H, int W, int b, int px, int ocb,
                  float* Xs, float* Ws, int t) {
    int p0 = px * 64, oc0 = ocb * 128;
    int HW = H * W;
    int tx = t & 15, ty = t >> 4;
    int Cp2 = C + 2;
    float acc[8][4] = {};
    for (int k0 = 0; k0 < C; k0 += 16) {
        int idx = t;
        #pragma unroll
        for (int i = 0; i < 4; i++, idx += 256) {
            int kk = idx >> 6, pp = idx & 63;
            Xs[kk * 64 + pp] = x[(size_t)(b * C + k0 + kk) * HW + p0 + pp];
        }
        idx = t;
        #pragma unroll
        for (int i = 0; i < 8; i++, idx += 256) {
            int ocp = idx >> 4, kk = idx & 15;
            Ws[kk * 132 + ocp] = w[(size_t)(oc0 + ocp) * Cp2 + k0 + kk];
        }
        __syncthreads();
        #pragma unroll
        for (int kk = 0; kk < 16; kk++) {
            float4 a4 = *reinterpret_cast<const float4*>(&Xs[kk * 64 + tx * 4]);
            float4 b0 = *reinterpret_cast<const float4*>(&Ws[kk * 132 + ty * 8]);
            float4 b1 = *reinterpret_cast<const float4*>(&Ws[kk * 132 + ty * 8 + 4]);
            float av[4] = { a4.x, a4.y, a4.z, a4.w };
            float bv[8] = { b0.x, b0.y, b0.z, b0.w, b1.x, b1.y, b1.z, b1.w };
            #pragma unroll
            for (int i = 0; i < 8; i++)
                #pragma unroll
                for (int j = 0; j < 4; j++)
                    acc[i][j] += bv[i] * av[j];
        }
        __syncthreads();
    }
    float invW = 2.f / (float)(W - 1), invH = 2.f / (float)(H - 1);
    #pragma unroll
    for (int i = 0; i < 8; i++) {
        int oc = oc0 + ty * 8 + i;
        float cx = w[(size_t)oc * Cp2 + C];
        float cy = w[(size_t)oc * Cp2 + C + 1];
        float bb = bias[oc];
        #pragma unroll
        for (int j = 0; j < 4; j++) {
            int p = p0 + tx * 4 + j;
            float xg = -1.f + (float)(p % W) * invW;
            float yg = -1.f + (float)(p / W) * invH;
            o[(size_t)(b * OC + oc) * HW + p] = acc[i][j] + cx * xg + cy * yg + bb;
        }
    }
}

__global__ __launch_bounds__(256) void conv_all_kernel(
    const float* __restrict__ w1, const float* __restrict__ b1,
    const float* __restrict__ w2, const float* __restrict__ b2,
    const float* __restrict__ w3, const float* __restrict__ b3) {
    __shared__ float Xs[16 * 64];
    __shared__ float Ws[16 * 132];
    int id = blockIdx.x, t = threadIdx.x;
    if (id < 512) {
        int b = id >> 7, rem = id & 127;
        conv_body(g_pool0, w1, b1, g_conv0, 256, 256, 64, 64,
                  b, rem & 63, rem >> 6, Xs, Ws, t);
    } else if (id < 768) {
        int v = id - 512;
        int b = v >> 6, rem = v & 63;
        conv_body(g_pool1, w2, b2, g_conv1, 512, 512, 32, 32,
                  b, rem & 15, rem >> 4, Xs, Ws, t);
    } else {
        int v = id - 768;
        int b = v >> 5, rem = v & 31;
        conv_body(g_pool2, w3, b3, g_conv2, 1024, 1024, 16, 16,
                  b, rem & 3, rem >> 2, Xs, Ws, t);
    }
}

// ===================== launch 3: phi (fused resize + out2 + feats) =====================
DI float bilin(const float* __restrict__ sp, int S, int p) {
    int h = p >> 6, ww = p & 63;
    float sc = (float)S / 64.f;
    float fy = ((float)h + 0.5f) * sc - 0.5f; fy = fminf(fmaxf(fy, 0.f), (float)(S - 1));
    float fx = ((float)ww + 0.5f) * sc - 0.5f; fx = fminf(fmaxf(fx, 0.f), (float)(S - 1));
    int y0 = (int)fy, x0 = (int)fx;
    int y1 = min(y0 + 1, S - 1), x1 = min(x0 + 1, S - 1);
    float wy = fy - (float)y0, wx = fx - (float)x0;
    float v00 = sp[y0 * S + x0], v01 = sp[y0 * S + x1];
    float v10 = sp[y1 * S + x0], v11 = sp[y1 * S + x1];
    return (1.f - wy) * ((1.f - wx) * v00 + wx * v01) + wy * ((1.f - wx) * v10 + wx * v11);
}

DI float fetch2(int b, int ch, int p) {
    if (ch < 256)  return g_conv0[(((size_t)(b * 256 + ch)) << 12) + p];
    if (ch < 768)  return bilin(&g_conv1[(size_t)(b * 512 + ch - 256) * 1024], 32, p);
    return bilin(&g_conv2[(size_t)(b * 1024 + ch - 768) * 256], 16, p);
}

__global__ void phi_all_kernel(float* __restrict__ out2) {
    __shared__ float tile[32][33];
    int b = blockIdx.z, ch0 = blockIdx.x * 32, p0 = blockIdx.y * 32;
    int tx = threadIdx.x, ty = threadIdx.y;
    for (int i = ty; i < 32; i += 8) {
        int ch = ch0 + i, p = p0 + tx;
        float v = fetch2(b, ch, p);
        tile[i][tx] = v;
        if (ch < 896)
            out2[(((size_t)(b * 896 + ch)) << 12) + p] = v;
    }
    __syncthreads();
    for (int i = ty; i < 32; i += 8) {
        int p = p0 + i;
        float v = tile[tx][i];
        g_phi[(size_t)(b * 4096 + p) * NCH + ch0 + tx] = __float2bfloat16(v);
        float s = v * v;
        s += __shfl_xor_sync(FULLMASK, s, 16);
        s += __shfl_xor_sync(FULLMASK, s, 8);
        s += __shfl_xor_sync(FULLMASK, s, 4);
        s += __shfl_xor_sync(FULLMASK, s, 2);
        s += __shfl_xor_sync(FULLMASK, s, 1);
        if (tx == 0) atomicAdd(&g_feats[b * 4096 + p], s);
    }
}

// ===================== launch 4: distance GEMM =====================
// CTA 64x128, 256 threads (8 warps 2x4), warp tile 32x32, K-chunk 32,
// 4-stage cp.async, 3 CTAs/SM (smem 60KB/CTA, regs <=85)
#define A_STRIDE 80
#define SA_BYTES (64*80)                 // 5120
#define SB_BYTES (128*80)                // 10240
#define STAGE_BYTES (SA_BYTES+SB_BYTES)  // 15360
#define NSTAGE 4
#define GEMM_SMEM (NSTAGE*STAGE_BYTES)   // 61440
#define NKCHUNK 56

DI void gemm_load_chunk(uint32_t sbuf, int m0, int n0, int k0, int t) {
    uint32_t sA = sbuf, sB = sbuf + SA_BYTES;
    {
        int row = t >> 2, seg = t & 3;
        cpasync16(sA + row * A_STRIDE + seg * 16,
                  &g_phi[(size_t)(m0 + row) * NCH + k0 + seg * 8]);
    }
    #pragma unroll
    for (int i = 0; i < 2; i++) {
        int idx = t + i * 256;
        int row = idx >> 2, seg = idx & 3;
        cpasync16(sB + row * A_STRIDE + seg * 16,
                  &g_ct[(size_t)(n0 + row) * NCH + k0 + seg * 8]);
    }
    cp_commit();
}

__global__ __launch_bounds__(256, 3) void gemm_kernel() {
    extern __shared__ __align__(16) char smem[];
    const uint32_t sbase = smem_u32(smem);
    int t = threadIdx.x, lane = t & 31, wid = t >> 5;
    int wm = wid & 1, wn = wid >> 1;     // 2 x 4 warp grid; warp tile 32x32
    int m0 = blockIdx.x * 64, n0 = blockIdx.y * 128;

    float c[2][4][4];
    #pragma unroll
    for (int i = 0; i < 2; i++)
        #pragma unroll
        for (int j = 0; j < 4; j++)
            #pragma unroll
            for (int r = 0; r < 4; r++) c[i][j][r] = 0.f;

    const uint32_t a_row = wm * 32 + (lane & 15);
    const uint32_t a_base = a_row * A_STRIDE + ((lane >> 4) * 16);
    const uint32_t b_row = wn * 32 + ((lane >> 4) * 8) + (lane & 7);
    const uint32_t b_base = b_row * A_STRIDE + (((lane >> 3) & 1) * 16);

    gemm_load_chunk(sbase, m0, n0, 0, t);
    gemm_load_chunk(sbase + STAGE_BYTES, m0, n0, 32, t);
    gemm_load_chunk(sbase + 2 * STAGE_BYTES, m0, n0, 64, t);

    int stage = 0;
    #pragma unroll 1
    for (int ck = 0; ck < NKCHUNK; ck++) {
        if (ck < NKCHUNK - 2) cp_wait2();
        else if (ck == NKCHUNK - 2) cp_wait1();
        else cp_wait0();
        __syncthreads();
        if (ck + 3 < NKCHUNK) {
            int ls = stage + 3; if (ls >= NSTAGE) ls -= NSTAGE;
            gemm_load_chunk(sbase + ls * STAGE_BYTES, m0, n0, (ck + 3) * 32, t);
        }
        uint32_t sA = sbase + stage * STAGE_BYTES;
        uint32_t sB = sA + SA_BYTES;
        #pragma unroll
        for (int ks = 0; ks < 2; ks++) {
            uint32_t a[2][4];
            #pragma unroll
            for (int mi = 0; mi < 2; mi++)
                ldsm4(a[mi], sA + a_base + mi * (16 * A_STRIDE) + ks * 32);
            uint32_t bfr[2][4];
            #pragma unroll
            for (int np = 0; np < 2; np++)
                ldsm4(bfr[np], sB + b_base + np * (16 * A_STRIDE) + ks * 32);
            #pragma unroll
            for (int mi = 0; mi < 2; mi++)
                #pragma unroll
                for (int np = 0; np < 2; np++) {
                    mma16816(c[mi][np * 2 + 0], a[mi], bfr[np][0], bfr[np][1]);
                    mma16816(c[mi][np * 2 + 1], a[mi], bfr[np][2], bfr[np][3]);
                }
        }
        if (++stage >= NSTAGE) stage = 0;
    }

    #pragma unroll
    for (int mi = 0; mi < 2; mi++) {
        int r0 = m0 + wm * 32 + mi * 16 + (lane >> 2);
        float f0 = g_feats[r0], f1 = g_feats[r0 + 8];
        #pragma unroll
        for (int ni = 0; ni < 4; ni++) {
            int cc = n0 + wn * 32 + ni * 8 + (lane & 3) * 2;
            float ce0 = g_cents[cc], ce1 = g_cents[cc + 1];
            float* dp = &g_dist2[(size_t)r0 * 4096 + cc];
            float2 v0 = { f0 + ce0 - 2.f * c[mi][ni][0], f0 + ce1 - 2.f * c[mi][ni][1] };
            float2 v1 = { f1 + ce0 - 2.f * c[mi][ni][2], f1 + ce1 - 2.f * c[mi][ni][3] };
            *reinterpret_cast<float2*>(dp) = v0;
            *reinterpret_cast<float2*>(dp + (size_t)8 * 4096) = v1;
        }
    }
}

// ===================== launch 5: top-200 per row (register-resident keys) =====================
__global__ __launch_bounds__(256) void topk_kernel(float* __restrict__ out) {
    __shared__ unsigned hist[256];
    __shared__ unsigned scan[256];
    __shared__ unsigned sh_want, sh_prefix;
    __shared__ unsigned cnt_lt;
    __shared__ float sel[256];

    int row = blockIdx.x;
    int t = threadIdx.x;
    int lane = t & 31;

    // 16 keys per thread, coalesced float4 loads
    float keys[16];
    const float4* src4 = reinterpret_cast<const float4*>(&g_dist2[(size_t)row * 4096]);
    #pragma unroll
    for (int j = 0; j < 4; j++) {
        float4 v = src4[t + j * 256];
        keys[j * 4 + 0] = v.x; keys[j * 4 + 1] = v.y;
        keys[j * 4 + 2] = v.z; keys[j * 4 + 3] = v.w;
    }
    if (t == 0) { sh_want = NNEI; sh_prefix = 0; cnt_lt = 0; }
    __syncthreads();

    #pragma unroll 1
    for (int pass = 0; pass < 4; pass++) {
        int shift = 24 - pass * 8;
        unsigned pfx = sh_prefix;
        unsigned want = sh_want;
        hist[t] = 0;
        __syncthreads();
        #pragma unroll
        for (int j = 0; j < 16; j++) {
            unsigned u = __float_as_uint(keys[j]);
            bool ok = (pass == 0) || ((u >> (shift + 8)) == pfx);
            unsigned d = ok ? ((u >> shift) & 255u) : 0x100u;
            unsigned m = __match_any_sync(FULLMASK, d);
            if (ok && ((m & ((1u << lane) - 1u)) == 0))
                atomicAdd(&hist[d], (unsigned)__popc(m));
        }
        __syncthreads();
        if (t < 32) {
            unsigned vals[8], tot = 0;
            #pragma unroll
            for (int i = 0; i < 8; i++) { vals[i] = hist[t * 8 + i]; tot += vals[i]; }
            unsigned run = tot;
            #pragma unroll
            for (int off = 1; off < 32; off <<= 1) {
                unsigned x = __shfl_up_sync(FULLMASK, run, off);
                if (t >= off) run += x;
            }
            unsigned acc = run - tot;
            #pragma unroll
            for (int i = 0; i < 8; i++) { acc += vals[i]; scan[t * 8 + i] = acc; }
        }
        __syncthreads();
        unsigned below = (t == 0) ? 0u : scan[t - 1];
        if (below < want && want <= scan[t]) {
            sh_want = want - below;
            sh_prefix = (pfx << 8) | (unsigned)t;
        }
        __syncthreads();
    }

    unsigned Tb = sh_prefix;
    float Tf = __uint_as_float(Tb);
    #pragma unroll
    for (int j = 0; j < 16; j++) {
        float v = keys[j];
        if (v < Tf) {
            unsigned pos = atomicAdd(&cnt_lt, 1u);
            sel[pos] = v;
        }
    }
    __syncthreads();
    unsigned base = cnt_lt;
    if ((unsigned)t >= base) sel[t] = (t < NNEI) ? Tf : __int_as_float(0x7f800000);
    __syncthreads();

    for (int k = 2; k <= 256; k <<= 1) {
        for (int j = k >> 1; j > 0; j >>= 1) {
            int ixj = t ^ j;
            if (ixj > t) {
                bool up = ((t & k) == 0);
                float a = sel[t], b = sel[ixj];
                if ((a > b) == up) { sel[t] = b; sel[ixj] = a; }
            }
            __syncthreads();
        }
    }

    if (t < NNEI) {
        int b = row >> 12, p = row & 4095;
        out[(((size_t)(b * NNEI + t)) << 12) + p] = sqrtf(sel[t]);
    }
}

// ===================== host launcher =====================
extern "C" void kernel_launch(void* const* d_in, const int* in_sizes, int n_in,
                              void* d_out, int out_size) {
    const float* p0 = (const float*)d_in[0];
    const float* p1 = (const float*)d_in[1];
    const float* p2 = (const float*)d_in[2];
    const float* w1 = (const float*)d_in[5];
    const float* b1 = (const float*)d_in[6];
    const float* w2 = (const float*)d_in[7];
    const float* b2 = (const float*)d_in[8];
    const float* w3 = (const float*)d_in[9];
    const float* b3 = (const float*)d_in[10];
    const float* Cm = (const float*)d_in[11];
    float* score = (float*)d_out;
    float* out2  = score + SCORE_ELEMS;

    static bool attr_set = false;
    if (!attr_set) {
        cudaFuncSetAttribute(gemm_kernel, cudaFuncAttributeMaxDynamicSharedMemorySize, GEMM_SMEM);
        attr_set = true;
    }

    prep_kernel<<<36032, 256>>>(p0, p1, p2, Cm);
    conv_all_kernel<<<896, 256>>>(w1, b1, w2, b2, w3, b3);
    phi_all_kernel<<<dim3(NCH/32, 128, 4), dim3(32, 8)>>>(out2);
    gemm_kernel<<<dim3(M_TOT/64, NCENT/128), 256, GEMM_SMEM>>>();
    topk_kernel<<<M_TOT, 256>>>(score);
}

// round 9
// speedup vs baseline: 1.2672x; 1.2672x over previous
#include <cuda_runtime.h>
#include <cuda_bf16.h>
#include <cstdint>

#define DI __device__ __forceinline__
#define FULLMASK 0xFFFFFFFFu

// ===================== problem dims =====================
#define NBATCH 4
#define NPIX   4096
#define NCH    1792
#define NCENT  4096
#define M_TOT  (NBATCH*NPIX)
#define NNEI   200
#define SCORE_ELEMS (NBATCH*NNEI*NPIX)

// ===================== scratch =====================
__device__ float g_pool0[4u*256*64*64];
__device__ float g_pool1[4u*512*32*32];
__device__ float g_pool2[4u*1024*16*16];
__device__ float g_conv0[4u*256*64*64];
__device__ float g_conv1[4u*512*32*32];
__device__ float g_conv2[4u*1024*16*16];
__device__ __nv_bfloat16 g_phi[(size_t)M_TOT*NCH];
__device__ __nv_bfloat16 g_ct [(size_t)NCENT*NCH];
__device__ float g_feats[M_TOT];
__device__ float g_cents[NCENT];
__device__ float g_dist2[(size_t)M_TOT*NCENT];

// ===================== PTX helpers (sm_100 baseline ISA) =====================
DI uint32_t smem_u32(const void* p) {
    uint32_t a;
    asm("{ .reg .u64 t; cvta.to.shared.u64 t, %1; cvt.u32.u64 %0, t; }" : "=r"(a) : "l"(p));
    return a;
}
DI void ldsm4(uint32_t* r, uint32_t a) {
    asm volatile("ldmatrix.sync.aligned.m8n8.x4.shared.b16 {%0,%1,%2,%3}, [%4];"
        : "=r"(r[0]), "=r"(r[1]), "=r"(r[2]), "=r"(r[3]) : "r"(a));
}
DI void mma16816(float* c, const uint32_t* a, uint32_t b0, uint32_t b1) {
    asm volatile("mma.sync.aligned.m16n8k16.row.col.f32.bf16.bf16.f32 "
        "{%0,%1,%2,%3}, {%4,%5,%6,%7}, {%8,%9}, {%0,%1,%2,%3};"
        : "+f"(c[0]), "+f"(c[1]), "+f"(c[2]), "+f"(c[3])
        : "r"(a[0]), "r"(a[1]), "r"(a[2]), "r"(a[3]), "r"(b0), "r"(b1));
}
DI void cpasync16(uint32_t dst, const void* src) {
    asm volatile("cp.async.cg.shared.global [%0], [%1], 16;" :: "r"(dst), "l"(src) : "memory");
}
DI void cp_commit() { asm volatile("cp.async.commit_group;" ::: "memory"); }
DI void cp_wait1()  { asm volatile("cp.async.wait_group 1;" ::: "memory"); }
DI void cp_wait0()  { asm volatile("cp.async.wait_group 0;" ::: "memory"); }

// ===================== launch 1: prep mega-kernel =====================
DI void pool_body(const float* __restrict__ x, float* __restrict__ y,
                  int H, int W, int idx) {
    int w = idx % W;
    int h = (idx / W) % H;
    int bc = idx / (W * H);
    const float* p = x + (size_t)bc * H * W;
    float s = 0.f;
    #pragma unroll
    for (int dy = -1; dy <= 1; dy++) {
        int hh = h + dy;
        if (hh < 0 || hh >= H) continue;
        #pragma unroll
        for (int dx = -1; dx <= 1; dx++) {
            int ww = w + dx;
            if (ww < 0 || ww >= W) continue;
            s += p[hh * W + ww];
        }
    }
    y[idx] = s * (1.0f / 9.0f);
}

__global__ __launch_bounds__(256) void prep_kernel(
    const float* __restrict__ p0, const float* __restrict__ p1,
    const float* __restrict__ p2, const float* __restrict__ C) {
    int bb = blockIdx.x, t = threadIdx.x;
    if (bb < 16384) {
        pool_body(p0, g_pool0, 64, 64, bb * 256 + t);
    } else if (bb < 24576) {
        pool_body(p1, g_pool1, 32, 32, (bb - 16384) * 256 + t);
    } else if (bb < 28672) {
        pool_body(p2, g_pool2, 16, 16, (bb - 24576) * 256 + t);
    } else if (bb < 35840) {
        __shared__ float tile[32][33];
        int id = bb - 28672;
        int j0 = (id & 127) * 32, k0 = (id >> 7) * 32;
        int tx = t & 31, ty = t >> 5;
        for (int i = ty; i < 32; i += 8)
            tile[i][tx] = C[(size_t)(k0 + i) * 4096 + j0 + tx];
        __syncthreads();
        for (int i = ty; i < 32; i += 8)
            g_ct[(size_t)(j0 + i) * NCH + k0 + tx] = __float2bfloat16(tile[tx][i]);
    } else if (bb < 35968) {
        __shared__ float red[256];
        int id = bb - 35840;
        int j = (id & 127) * 32 + (t & 31);
        int kp = t >> 5;
        float s = 0.f;
        int kbeg = kp * 224, kend = kbeg + 224;
        for (int k = kbeg; k < kend; k++) {
            float v = C[(size_t)k * 4096 + j];
            s += v * v;
        }
        red[t] = s;
        __syncthreads();
        if (t < 32) {
            float acc = red[t];
            #pragma unroll
            for (int i = 1; i < 8; i++) acc += red[t + i * 32];
            g_cents[j] = acc;
        }
    } else {
        g_feats[(bb - 35968) * 256 + t] = 0.f;
    }
}

// ===================== launch 2: coord-conv (128oc x 64px tile, 8x4/thread) =====================
DI void conv_body(const float* __restrict__ x, const float* __restrict__ w,
                  const float* __restrict__ bias, float* __restrict__ o,
                  int C, int OC, int H, int W, int b, int px, int ocb,
                  float* Xs, float* Ws, int t) {
    int p0 = px * 64, oc0 = ocb * 128;
    int HW = H * W;
    int tx = t & 15, ty = t >> 4;
    int Cp2 = C + 2;
    float acc[8][4] = {};
    for (int k0 = 0; k0 < C; k0 += 16) {
        int idx = t;
        #pragma unroll
        for (int i = 0; i < 4; i++, idx += 256) {
            int kk = idx >> 6, pp = idx & 63;
            Xs[kk * 64 + pp] = x[(size_t)(b * C + k0 + kk) * HW + p0 + pp];
        }
        idx = t;
        #pragma unroll
        for (int i = 0; i < 8; i++, idx += 256) {
            int ocp = idx >> 4, kk = idx & 15;
            Ws[kk * 132 + ocp] = w[(size_t)(oc0 + ocp) * Cp2 + k0 + kk];
        }
        __syncthreads();
        #pragma unroll
        for (int kk = 0; kk < 16; kk++) {
            float4 a4 = *reinterpret_cast<const float4*>(&Xs[kk * 64 + tx * 4]);
            float4 b0 = *reinterpret_cast<const float4*>(&Ws[kk * 132 + ty * 8]);
            float4 b1 = *reinterpret_cast<const float4*>(&Ws[kk * 132 + ty * 8 + 4]);
            float av[4] = { a4.x, a4.y, a4.z, a4.w };
            float bv[8] = { b0.x, b0.y, b0.z, b0.w, b1.x, b1.y, b1.z, b1.w };
            #pragma unroll
            for (int i = 0; i < 8; i++)
                #pragma unroll
                for (int j = 0; j < 4; j++)
                    acc[i][j] += bv[i] * av[j];
        }
        __syncthreads();
    }
    float invW = 2.f / (float)(W - 1), invH = 2.f / (float)(H - 1);
    #pragma unroll
    for (int i = 0; i < 8; i++) {
        int oc = oc0 + ty * 8 + i;
        float cx = w[(size_t)oc * Cp2 + C];
        float cy = w[(size_t)oc * Cp2 + C + 1];
        float bb = bias[oc];
        #pragma unroll
        for (int j = 0; j < 4; j++) {
            int p = p0 + tx * 4 + j;
            float xg = -1.f + (float)(p % W) * invW;
            float yg = -1.f + (float)(p / W) * invH;
            o[(size_t)(b * OC + oc) * HW + p] = acc[i][j] + cx * xg + cy * yg + bb;
        }
    }
}

__global__ __launch_bounds__(256) void conv_all_kernel(
    const float* __restrict__ w1, const float* __restrict__ b1,
    const float* __restrict__ w2, const float* __restrict__ b2,
    const float* __restrict__ w3, const float* __restrict__ b3) {
    __shared__ float Xs[16 * 64];
    __shared__ float Ws[16 * 132];
    int id = blockIdx.x, t = threadIdx.x;
    if (id < 512) {
        int b = id >> 7, rem = id & 127;
        conv_body(g_pool0, w1, b1, g_conv0, 256, 256, 64, 64,
                  b, rem & 63, rem >> 6, Xs, Ws, t);
    } else if (id < 768) {
        int v = id - 512;
        int b = v >> 6, rem = v & 63;
        conv_body(g_pool1, w2, b2, g_conv1, 512, 512, 32, 32,
                  b, rem & 15, rem >> 4, Xs, Ws, t);
    } else {
        int v = id - 768;
        int b = v >> 5, rem = v & 31;
        conv_body(g_pool2, w3, b3, g_conv2, 1024, 1024, 16, 16,
                  b, rem & 3, rem >> 2, Xs, Ws, t);
    }
}

// ===================== launch 3: phi (fused resize + out2 + feats) =====================
DI float bilin(const float* __restrict__ sp, int S, int p) {
    int h = p >> 6, ww = p & 63;
    float sc = (float)S / 64.f;
    float fy = ((float)h + 0.5f) * sc - 0.5f; fy = fminf(fmaxf(fy, 0.f), (float)(S - 1));
    float fx = ((float)ww + 0.5f) * sc - 0.5f; fx = fminf(fmaxf(fx, 0.f), (float)(S - 1));
    int y0 = (int)fy, x0 = (int)fx;
    int y1 = min(y0 + 1, S - 1), x1 = min(x0 + 1, S - 1);
    float wy = fy - (float)y0, wx = fx - (float)x0;
    float v00 = sp[y0 * S + x0], v01 = sp[y0 * S + x1];
    float v10 = sp[y1 * S + x0], v11 = sp[y1 * S + x1];
    return (1.f - wy) * ((1.f - wx) * v00 + wx * v01) + wy * ((1.f - wx) * v10 + wx * v11);
}

DI float fetch2(int b, int ch, int p) {
    if (ch < 256)  return g_conv0[(((size_t)(b * 256 + ch)) << 12) + p];
    if (ch < 768)  return bilin(&g_conv1[(size_t)(b * 512 + ch - 256) * 1024], 32, p);
    return bilin(&g_conv2[(size_t)(b * 1024 + ch - 768) * 256], 16, p);
}

__global__ void phi_all_kernel(float* __restrict__ out2) {
    __shared__ float tile[32][33];
    int b = blockIdx.z, ch0 = blockIdx.x * 32, p0 = blockIdx.y * 32;
    int tx = threadIdx.x, ty = threadIdx.y;
    for (int i = ty; i < 32; i += 8) {
        int ch = ch0 + i, p = p0 + tx;
        float v = fetch2(b, ch, p);
        tile[i][tx] = v;
        if (ch < 896)
            out2[(((size_t)(b * 896 + ch)) << 12) + p] = v;
    }
    __syncthreads();
    for (int i = ty; i < 32; i += 8) {
        int p = p0 + i;
        float v = tile[tx][i];
        g_phi[(size_t)(b * 4096 + p) * NCH + ch0 + tx] = __float2bfloat16(v);
        float s = v * v;
        s += __shfl_xor_sync(FULLMASK, s, 16);
        s += __shfl_xor_sync(FULLMASK, s, 8);
        s += __shfl_xor_sync(FULLMASK, s, 4);
        s += __shfl_xor_sync(FULLMASK, s, 2);
        s += __shfl_xor_sync(FULLMASK, s, 1);
        if (tx == 0) atomicAdd(&g_feats[b * 4096 + p], s);
    }
}

// ===================== launch 4: distance GEMM (R7 config) =====================
// CTA 128x128, 256 threads (8 warps 2x4), warp tile 64x32, K-chunk 64,
// 3-stage cp.async, 2 CTAs/SM
#define A_STRIDE 144
#define SA_BYTES (128*144)
#define STAGE_BYTES (2*SA_BYTES)          // A + B = 36864
#define NSTAGE 3
#define GEMM_SMEM (NSTAGE*STAGE_BYTES)    // 110592
#define NKCHUNK 28

DI void gemm_load_chunk(uint32_t sbuf, int m0, int n0, int k0, int t) {
    uint32_t sA = sbuf, sB = sbuf + SA_BYTES;
    #pragma unroll
    for (int i = 0; i < 4; i++) {
        int idx = t + i * 256;
        int row = idx >> 3, seg = idx & 7;
        cpasync16(sA + row * A_STRIDE + seg * 16,
                  &g_phi[(size_t)(m0 + row) * NCH + k0 + seg * 8]);
    }
    #pragma unroll
    for (int i = 0; i < 4; i++) {
        int idx = t + i * 256;
        int row = idx >> 3, seg = idx & 7;
        cpasync16(sB + row * A_STRIDE + seg * 16,
                  &g_ct[(size_t)(n0 + row) * NCH + k0 + seg * 8]);
    }
    cp_commit();
}

__global__ __launch_bounds__(256, 2) void gemm_kernel() {
    extern __shared__ __align__(16) char smem[];
    const uint32_t sbase = smem_u32(smem);
    int t = threadIdx.x, lane = t & 31, wid = t >> 5;
    int wm = wid & 1, wn = wid >> 1;     // 2 x 4 warp grid; warp tile 64x32
    int m0 = blockIdx.x * 128, n0 = blockIdx.y * 128;

    float c[4][4][4];
    #pragma unroll
    for (int i = 0; i < 4; i++)
        #pragma unroll
        for (int j = 0; j < 4; j++)
            #pragma unroll
            for (int r = 0; r < 4; r++) c[i][j][r] = 0.f;

    const uint32_t a_row = wm * 64 + (lane & 15);
    const uint32_t a_base = a_row * A_STRIDE + ((lane >> 4) * 16);
    const uint32_t b_row = wn * 32 + ((lane >> 4) * 8) + (lane & 7);
    const uint32_t b_base = b_row * A_STRIDE + (((lane >> 3) & 1) * 16);

    gemm_load_chunk(sbase, m0, n0, 0, t);
    gemm_load_chunk(sbase + STAGE_BYTES, m0, n0, 64, t);

    int stage = 0;
    #pragma unroll 1
    for (int ck = 0; ck < NKCHUNK; ck++) {
        if (ck == NKCHUNK - 1) cp_wait0(); else cp_wait1();
        __syncthreads();
        if (ck + 2 < NKCHUNK) {
            int ls = stage + 2; if (ls >= NSTAGE) ls -= NSTAGE;
            gemm_load_chunk(sbase + ls * STAGE_BYTES, m0, n0, (ck + 2) * 64, t);
        }
        uint32_t sA = sbase + stage * STAGE_BYTES;
        uint32_t sB = sA + SA_BYTES;
        #pragma unroll
        for (int ks = 0; ks < 4; ks++) {
            uint32_t a[4][4];
            #pragma unroll
            for (int mi = 0; mi < 4; mi++)
                ldsm4(a[mi], sA + a_base + mi * (16 * A_STRIDE) + ks * 32);
            uint32_t bfr[2][4];
            #pragma unroll
            for (int np = 0; np < 2; np++)
                ldsm4(bfr[np], sB + b_base + np * (16 * A_STRIDE) + ks * 32);
            #pragma unroll
            for (int mi = 0; mi < 4; mi++)
                #pragma unroll
                for (int np = 0; np < 2; np++) {
                    mma16816(c[mi][np * 2 + 0], a[mi], bfr[np][0], bfr[np][1]);
                    mma16816(c[mi][np * 2 + 1], a[mi], bfr[np][2], bfr[np][3]);
                }
        }
        if (++stage >= NSTAGE) stage = 0;
    }

    #pragma unroll
    for (int mi = 0; mi < 4; mi++) {
        int r0 = m0 + wm * 64 + mi * 16 + (lane >> 2);
        float f0 = g_feats[r0], f1 = g_feats[r0 + 8];
        #pragma unroll
        for (int ni = 0; ni < 4; ni++) {
            int cc = n0 + wn * 32 + ni * 8 + (lane & 3) * 2;
            float ce0 = g_cents[cc], ce1 = g_cents[cc + 1];
            float* dp = &g_dist2[(size_t)r0 * 4096 + cc];
            float2 v0 = { f0 + ce0 - 2.f * c[mi][ni][0], f0 + ce1 - 2.f * c[mi][ni][1] };
            float2 v1 = { f1 + ce0 - 2.f * c[mi][ni][2], f1 + ce1 - 2.f * c[mi][ni][3] };
            *reinterpret_cast<float2*>(dp) = v0;
            *reinterpret_cast<float2*>(dp + (size_t)8 * 4096) = v1;
        }
    }
}

// ===================== launch 5: top-200 per row =====================
__global__ __launch_bounds__(256) void topk_kernel(float* __restrict__ out) {
    __shared__ unsigned hist[256];
    __shared__ unsigned scan[256];
    __shared__ unsigned sh_want, sh_prefix;
    __shared__ unsigned cnt_lt;
    __shared__ float sel[256];

    int row = blockIdx.x;
    int t = threadIdx.x;
    int lane = t & 31;

    float keys[16];
    const float4* src4 = reinterpret_cast<const float4*>(&g_dist2[(size_t)row * 4096]);
    #pragma unroll
    for (int j = 0; j < 4; j++) {
        float4 v = src4[t + j * 256];
        keys[j * 4 + 0] = v.x; keys[j * 4 + 1] = v.y;
        keys[j * 4 + 2] = v.z; keys[j * 4 + 3] = v.w;
    }
    if (t == 0) { sh_want = NNEI; sh_prefix = 0; cnt_lt = 0; }
    __syncthreads();

    // pass 0: exponent bits cluster -> warp-aggregated atomics
    {
        hist[t] = 0;
        __syncthreads();
        #pragma unroll
        for (int j = 0; j < 16; j++) {
            unsigned d = __float_as_uint(keys[j]) >> 24;
            unsigned m = __match_any_sync(FULLMASK, d);
            if ((m & ((1u << lane) - 1u)) == 0)
                atomicAdd(&hist[d], (unsigned)__popc(m));
        }
        __syncthreads();
        if (t < 32) {
            unsigned vals[8], tot = 0;
            #pragma unroll
            for (int i = 0; i < 8; i++) { vals[i] = hist[t * 8 + i]; tot += vals[i]; }
            unsigned run = tot;
            #pragma unroll
            for (int off = 1; off < 32; off <<= 1) {
                unsigned x = __shfl_up_sync(FULLMASK, run, off);
                if (t >= off) run += x;
            }
            unsigned acc = run - tot;
            #pragma unroll
            for (int i = 0; i < 8; i++) { acc += vals[i]; scan[t * 8 + i] = acc; }
        }
        __syncthreads();
        unsigned below = (t == 0) ? 0u : scan[t - 1];
        if (below < NNEI && NNEI <= scan[t]) {
            sh_want = NNEI - below;
            sh_prefix = (unsigned)t;
        }
        __syncthreads();
    }

    // passes 1-3: mantissa bits are spread -> plain atomics (match_any is pure overhead)
    #pragma unroll 1
    for (int pass = 1; pass < 4; pass++) {
        int shift = 24 - pass * 8;
        unsigned pfx = sh_prefix;
        unsigned want = sh_want;
        hist[t] = 0;
        __syncthreads();
        #pragma unroll
        for (int j = 0; j < 16; j++) {
            unsigned u = __float_as_uint(keys[j]);
            if ((u >> (shift + 8)) == pfx)
                atomicAdd(&hist[(u >> shift) & 255u], 1u);
        }
        __syncthreads();
        if (t < 32) {
            unsigned vals[8], tot = 0;
            #pragma unroll
            for (int i = 0; i < 8; i++) { vals[i] = hist[t * 8 + i]; tot += vals[i]; }
            unsigned run = tot;
            #pragma unroll
            for (int off = 1; off < 32; off <<= 1) {
                unsigned x = __shfl_up_sync(FULLMASK, run, off);
                if (t >= off) run += x;
            }
            unsigned acc = run - tot;
            #pragma unroll
            for (int i = 0; i < 8; i++) { acc += vals[i]; scan[t * 8 + i] = acc; }
        }
        __syncthreads();
        unsigned below = (t == 0) ? 0u : scan[t - 1];
        if (below < want && want <= scan[t]) {
            sh_want = want - below;
            sh_prefix = (pfx << 8) | (unsigned)t;
        }
        __syncthreads();
    }

    unsigned Tb = sh_prefix;
    float Tf = __uint_as_float(Tb);
    #pragma unroll
    for (int j = 0; j < 16; j++) {
        float v = keys[j];
        if (v < Tf) {
            unsigned pos = atomicAdd(&cnt_lt, 1u);
            sel[pos] = v;
        }
    }
    __syncthreads();
    unsigned base = cnt_lt;
    if ((unsigned)t >= base) sel[t] = (t < NNEI) ? Tf : __int_as_float(0x7f800000);
    __syncthreads();

    for (int k = 2; k <= 256; k <<= 1) {
        for (int j = k >> 1; j > 0; j >>= 1) {
            int ixj = t ^ j;
            if (ixj > t) {
                bool up = ((t & k) == 0);
                float a = sel[t], b = sel[ixj];
                if ((a > b) == up) { sel[t] = b; sel[ixj] = a; }
            }
            __syncthreads();
        }
    }

    if (t < NNEI) {
        int b = row >> 12, p = row & 4095;
        out[(((size_t)(b * NNEI + t)) << 12) + p] = sqrtf(sel[t]);
    }
}

// ===================== host launcher =====================
extern "C" void kernel_launch(void* const* d_in, const int* in_sizes, int n_in,
                              void* d_out, int out_size) {
    const float* p0 = (const float*)d_in[0];
    const float* p1 = (const float*)d_in[1];
    const float* p2 = (const float*)d_in[2];
    const float* w1 = (const float*)d_in[5];
    const float* b1 = (const float*)d_in[6];
    const float* w2 = (const float*)d_in[7];
    const float* b2 = (const float*)d_in[8];
    const float* w3 = (const float*)d_in[9];
    const float* b3 = (const float*)d_in[10];
    const float* Cm = (const float*)d_in[11];
    float* score = (float*)d_out;
    float* out2  = score + SCORE_ELEMS;

    static bool attr_set = false;
    if (!attr_set) {
        cudaFuncSetAttribute(gemm_kernel, cudaFuncAttributeMaxDynamicSharedMemorySize, GEMM_SMEM);
        attr_set = true;
    }

    prep_kernel<<<36032, 256>>>(p0, p1, p2, Cm);
    conv_all_kernel<<<896, 256>>>(w1, b1, w2, b2, w3, b3);
    phi_all_kernel<<<dim3(NCH/32, 128, 4), dim3(32, 8)>>>(out2);
    gemm_kernel<<<dim3(M_TOT/128, NCENT/128), 256, GEMM_SMEM>>>();
    topk_kernel<<<M_TOT, 256>>>(score);
}

// round 10
// speedup vs baseline: 1.2784x; 1.0089x over previous
#include <cuda_runtime.h>
#include <cuda_bf16.h>
#include <cstdint>

#define DI __device__ __forceinline__
#define FULLMASK 0xFFFFFFFFu

// ===================== problem dims =====================
#define NBATCH 4
#define NPIX   4096
#define NCH    1792
#define NCENT  4096
#define M_TOT  (NBATCH*NPIX)
#define NNEI   200
#define SCORE_ELEMS (NBATCH*NNEI*NPIX)

// ===================== scratch =====================
__device__ float g_pool0[4u*256*64*64];
__device__ float g_pool1[4u*512*32*32];
__device__ float g_pool2[4u*1024*16*16];
__device__ float g_conv0[4u*256*64*64];
__device__ float g_conv1[4u*512*32*32];
__device__ float g_conv2[4u*1024*16*16];
__device__ __nv_bfloat16 g_phi[(size_t)M_TOT*NCH];
__device__ __nv_bfloat16 g_ct [(size_t)NCENT*NCH];
__device__ float g_feats[M_TOT];
__device__ float g_cents[NCENT];
__device__ float g_dist2[(size_t)M_TOT*NCENT];

// ===================== PTX helpers (sm_100 baseline ISA) =====================
DI uint32_t smem_u32(const void* p) {
    uint32_t a;
    asm("{ .reg .u64 t; cvta.to.shared.u64 t, %1; cvt.u32.u64 %0, t; }" : "=r"(a) : "l"(p));
    return a;
}
DI void ldsm4(uint32_t* r, uint32_t a) {
    asm volatile("ldmatrix.sync.aligned.m8n8.x4.shared.b16 {%0,%1,%2,%3}, [%4];"
        : "=r"(r[0]), "=r"(r[1]), "=r"(r[2]), "=r"(r[3]) : "r"(a));
}
DI void mma16816(float* c, const uint32_t* a, uint32_t b0, uint32_t b1) {
    asm volatile("mma.sync.aligned.m16n8k16.row.col.f32.bf16.bf16.f32 "
        "{%0,%1,%2,%3}, {%4,%5,%6,%7}, {%8,%9}, {%0,%1,%2,%3};"
        : "+f"(c[0]), "+f"(c[1]), "+f"(c[2]), "+f"(c[3])
        : "r"(a[0]), "r"(a[1]), "r"(a[2]), "r"(a[3]), "r"(b0), "r"(b1));
}
DI void cpasync16(uint32_t dst, const void* src) {
    asm volatile("cp.async.cg.shared.global [%0], [%1], 16;" :: "r"(dst), "l"(src) : "memory");
}
DI void cp_commit() { asm volatile("cp.async.commit_group;" ::: "memory"); }
DI void cp_wait1()  { asm volatile("cp.async.wait_group 1;" ::: "memory"); }
DI void cp_wait0()  { asm volatile("cp.async.wait_group 0;" ::: "memory"); }

// ===================== launch 1: prep mega-kernel =====================
DI void pool_body(const float* __restrict__ x, float* __restrict__ y,
                  int H, int W, int idx) {
    int w = idx % W;
    int h = (idx / W) % H;
    int bc = idx / (W * H);
    const float* p = x + (size_t)bc * H * W;
    float s = 0.f;
    #pragma unroll
    for (int dy = -1; dy <= 1; dy++) {
        int hh = h + dy;
        if (hh < 0 || hh >= H) continue;
        #pragma unroll
        for (int dx = -1; dx <= 1; dx++) {
            int ww = w + dx;
            if (ww < 0 || ww >= W) continue;
            s += p[hh * W + ww];
        }
    }
    y[idx] = s * (1.0f / 9.0f);
}

__global__ __launch_bounds__(256) void prep_kernel(
    const float* __restrict__ p0, const float* __restrict__ p1,
    const float* __restrict__ p2, const float* __restrict__ C) {
    int bb = blockIdx.x, t = threadIdx.x;
    if (bb < 16384) {
        pool_body(p0, g_pool0, 64, 64, bb * 256 + t);
    } else if (bb < 24576) {
        pool_body(p1, g_pool1, 32, 32, (bb - 16384) * 256 + t);
    } else if (bb < 28672) {
        pool_body(p2, g_pool2, 16, 16, (bb - 24576) * 256 + t);
    } else if (bb < 35840) {
        __shared__ float tile[32][33];
        int id = bb - 28672;
        int j0 = (id & 127) * 32, k0 = (id >> 7) * 32;
        int tx = t & 31, ty = t >> 5;
        for (int i = ty; i < 32; i += 8)
            tile[i][tx] = C[(size_t)(k0 + i) * 4096 + j0 + tx];
        __syncthreads();
        for (int i = ty; i < 32; i += 8)
            g_ct[(size_t)(j0 + i) * NCH + k0 + tx] = __float2bfloat16(tile[tx][i]);
    } else {
        __shared__ float red[256];
        int id = bb - 35840;
        int j = (id & 127) * 32 + (t & 31);
        int kp = t >> 5;
        float s = 0.f;
        int kbeg = kp * 224, kend = kbeg + 224;
        for (int k = kbeg; k < kend; k++) {
            float v = C[(size_t)k * 4096 + j];
            s += v * v;
        }
        red[t] = s;
        __syncthreads();
        if (t < 32) {
            float acc = red[t];
            #pragma unroll
            for (int i = 1; i < 8; i++) acc += red[t + i * 32];
            g_cents[j] = acc;
        }
    }
}

// ===================== launch 2: coord-conv (templated oc tile) =====================
template<int NOC>
DI void conv_body(const float* __restrict__ x, const float* __restrict__ w,
                  const float* __restrict__ bias, float* __restrict__ o,
                  int C, int OC, int H, int W, int b, int px, int ocb,
                  float* Xs, float* Ws, int t) {
    int p0 = px * 64, oc0 = ocb * (NOC * 16);
    int HW = H * W;
    int tx = t & 15, ty = t >> 4;
    int Cp2 = C + 2;
    float acc[NOC][4] = {};
    for (int k0 = 0; k0 < C; k0 += 16) {
        int idx = t;
        #pragma unroll
        for (int i = 0; i < 4; i++, idx += 256) {
            int kk = idx >> 6, pp = idx & 63;
            Xs[kk * 64 + pp] = x[(size_t)(b * C + k0 + kk) * HW + p0 + pp];
        }
        idx = t;
        #pragma unroll
        for (int i = 0; i < NOC; i++, idx += 256) {
            int ocp = idx >> 4, kk = idx & 15;
            Ws[kk * 132 + ocp] = w[(size_t)(oc0 + ocp) * Cp2 + k0 + kk];
        }
        __syncthreads();
        #pragma unroll
        for (int kk = 0; kk < 16; kk++) {
            float4 a4 = *reinterpret_cast<const float4*>(&Xs[kk * 64 + tx * 4]);
            float av[4] = { a4.x, a4.y, a4.z, a4.w };
            float bv[NOC];
            #pragma unroll
            for (int q = 0; q < NOC / 4; q++) {
                float4 b4 = *reinterpret_cast<const float4*>(&Ws[kk * 132 + ty * NOC + q * 4]);
                bv[q * 4 + 0] = b4.x; bv[q * 4 + 1] = b4.y;
                bv[q * 4 + 2] = b4.z; bv[q * 4 + 3] = b4.w;
            }
            #pragma unroll
            for (int i = 0; i < NOC; i++)
                #pragma unroll
                for (int j = 0; j < 4; j++)
                    acc[i][j] += bv[i] * av[j];
        }
        __syncthreads();
    }
    float invW = 2.f / (float)(W - 1), invH = 2.f / (float)(H - 1);
    #pragma unroll
    for (int i = 0; i < NOC; i++) {
        int oc = oc0 + ty * NOC + i;
        float cx = w[(size_t)oc * Cp2 + C];
        float cy = w[(size_t)oc * Cp2 + C + 1];
        float bb = bias[oc];
        #pragma unroll
        for (int j = 0; j < 4; j++) {
            int p = p0 + tx * 4 + j;
            float xg = -1.f + (float)(p % W) * invW;
            float yg = -1.f + (float)(p / W) * invH;
            o[(size_t)(b * OC + oc) * HW + p] = acc[i][j] + cx * xg + cy * yg + bb;
        }
    }
}

// blocks (heavy first): [0,256) L2 (64oc x 64px) | [256,512) L1 (128oc x 64px) | [512,1024) L0
__global__ __launch_bounds__(256) void conv_all_kernel(
    const float* __restrict__ w1, const float* __restrict__ b1,
    const float* __restrict__ w2, const float* __restrict__ b2,
    const float* __restrict__ w3, const float* __restrict__ b3) {
    __shared__ float Xs[16 * 64];
    __shared__ float Ws[16 * 132];
    int id = blockIdx.x, t = threadIdx.x;
    if (id < 256) {
        int b = id >> 6, rem = id & 63;   // 4px x 16 ocb
        conv_body<4>(g_pool2, w3, b3, g_conv2, 1024, 1024, 16, 16,
                     b, rem & 3, rem >> 2, Xs, Ws, t);
    } else if (id < 512) {
        int v = id - 256;
        int b = v >> 6, rem = v & 63;     // 16px x 4 ocb
        conv_body<8>(g_pool1, w2, b2, g_conv1, 512, 512, 32, 32,
                     b, rem & 15, rem >> 4, Xs, Ws, t);
    } else {
        int v = id - 512;
        int b = v >> 7, rem = v & 127;    // 64px x 2 ocb
        conv_body<8>(g_pool0, w1, b1, g_conv0, 256, 256, 64, 64,
                     b, rem & 63, rem >> 6, Xs, Ws, t);
    }
}

// ===================== launch 3: phi (fused resize + out2 + feats, no atomics) =====================
DI float bilin(const float* __restrict__ sp, int S, int p) {
    int h = p >> 6, ww = p & 63;
    float sc = (float)S / 64.f;
    float fy = ((float)h + 0.5f) * sc - 0.5f; fy = fminf(fmaxf(fy, 0.f), (float)(S - 1));
    float fx = ((float)ww + 0.5f) * sc - 0.5f; fx = fminf(fmaxf(fx, 0.f), (float)(S - 1));
    int y0 = (int)fy, x0 = (int)fx;
    int y1 = min(y0 + 1, S - 1), x1 = min(x0 + 1, S - 1);
    float wy = fy - (float)y0, wx = fx - (float)x0;
    float v00 = sp[y0 * S + x0], v01 = sp[y0 * S + x1];
    float v10 = sp[y1 * S + x0], v11 = sp[y1 * S + x1];
    return (1.f - wy) * ((1.f - wx) * v00 + wx * v01) + wy * ((1.f - wx) * v10 + wx * v11);
}

DI float fetch2(int b, int ch, int p) {
    if (ch < 256)  return g_conv0[(((size_t)(b * 256 + ch)) << 12) + p];
    if (ch < 768)  return bilin(&g_conv1[(size_t)(b * 512 + ch - 256) * 1024], 32, p);
    return bilin(&g_conv2[(size_t)(b * 1024 + ch - 768) * 256], 16, p);
}

// grid (128 p-tiles, 4 b), block 256 = 32x8; loops all 56 channel chunks
__global__ __launch_bounds__(256) void phi_all_kernel(float* __restrict__ out2) {
    __shared__ float tile[32][33];
    __shared__ float fsmem[32];
    int b = blockIdx.y, p0 = blockIdx.x * 32;
    int tx = threadIdx.x & 31, ty = threadIdx.x >> 5;
    if (threadIdx.x < 32) fsmem[threadIdx.x] = 0.f;
    __syncthreads();
    #pragma unroll 1
    for (int ch0 = 0; ch0 < NCH; ch0 += 32) {
        for (int i = ty; i < 32; i += 8) {
            int ch = ch0 + i, p = p0 + tx;
            float v = fetch2(b, ch, p);
            tile[i][tx] = v;
            if (ch < 896)
                out2[(((size_t)(b * 896 + ch)) << 12) + p] = v;
        }
        __syncthreads();
        for (int i = ty; i < 32; i += 8) {
            int p = p0 + i;
            float v = tile[tx][i];
            g_phi[(size_t)(b * 4096 + p) * NCH + ch0 + tx] = __float2bfloat16(v);
            float s = v * v;
            s += __shfl_xor_sync(FULLMASK, s, 16);
            s += __shfl_xor_sync(FULLMASK, s, 8);
            s += __shfl_xor_sync(FULLMASK, s, 4);
            s += __shfl_xor_sync(FULLMASK, s, 2);
            s += __shfl_xor_sync(FULLMASK, s, 1);
            if (tx == 0) fsmem[i] += s;   // unique writer per row i (warp ty owns i = ty+8k)
        }
        __syncthreads();
    }
    if (threadIdx.x < 32)
        g_feats[b * 4096 + p0 + threadIdx.x] = fsmem[threadIdx.x];
}

// ===================== launch 4: distance GEMM (R7 config + B-frag pipeline) =====================
#define A_STRIDE 144
#define SA_BYTES (128*144)
#define STAGE_BYTES (2*SA_BYTES)          // 36864
#define NSTAGE 3
#define GEMM_SMEM (NSTAGE*STAGE_BYTES)    // 110592
#define NKCHUNK 28

DI void gemm_load_chunk(uint32_t sbuf, int m0, int n0, int k0, int t) {
    uint32_t sA = sbuf, sB = sbuf + SA_BYTES;
    #pragma unroll
    for (int i = 0; i < 4; i++) {
        int idx = t + i * 256;
        int row = idx >> 3, seg = idx & 7;
        cpasync16(sA + row * A_STRIDE + seg * 16,
                  &g_phi[(size_t)(m0 + row) * NCH + k0 + seg * 8]);
    }
    #pragma unroll
    for (int i = 0; i < 4; i++) {
        int idx = t + i * 256;
        int row = idx >> 3, seg = idx & 7;
        cpasync16(sB + row * A_STRIDE + seg * 16,
                  &g_ct[(size_t)(n0 + row) * NCH + k0 + seg * 8]);
    }
    cp_commit();
}

__global__ __launch_bounds__(256, 2) void gemm_kernel() {
    extern __shared__ __align__(16) char smem[];
    const uint32_t sbase = smem_u32(smem);
    int t = threadIdx.x, lane = t & 31, wid = t >> 5;
    int wm = wid & 1, wn = wid >> 1;     // 2 x 4 warp grid; warp tile 64x32
    int m0 = blockIdx.x * 128, n0 = blockIdx.y * 128;

    float c[4][4][4];
    #pragma unroll
    for (int i = 0; i < 4; i++)
        #pragma unroll
        for (int j = 0; j < 4; j++)
            #pragma unroll
            for (int r = 0; r < 4; r++) c[i][j][r] = 0.f;

    const uint32_t a_row = wm * 64 + (lane & 15);
    const uint32_t a_base = a_row * A_STRIDE + ((lane >> 4) * 16);
    const uint32_t b_row = wn * 32 + ((lane >> 4) * 8) + (lane & 7);
    const uint32_t b_base = b_row * A_STRIDE + (((lane >> 3) & 1) * 16);

    gemm_load_chunk(sbase, m0, n0, 0, t);
    gemm_load_chunk(sbase + STAGE_BYTES, m0, n0, 64, t);

    int stage = 0;
    #pragma unroll 1
    for (int ck = 0; ck < NKCHUNK; ck++) {
        if (ck == NKCHUNK - 1) cp_wait0(); else cp_wait1();
        __syncthreads();
        if (ck + 2 < NKCHUNK) {
            int ls = stage + 2; if (ls >= NSTAGE) ls -= NSTAGE;
            gemm_load_chunk(sbase + ls * STAGE_BYTES, m0, n0, (ck + 2) * 64, t);
        }
        uint32_t sA = sbase + stage * STAGE_BYTES;
        uint32_t sB = sA + SA_BYTES;

        // B-fragment double buffer across ks
        uint32_t bf[2][2][4];
        ldsm4(bf[0][0], sB + b_base + 0 * (16 * A_STRIDE));
        ldsm4(bf[0][1], sB + b_base + 1 * (16 * A_STRIDE));
        #pragma unroll
        for (int ks = 0; ks < 4; ks++) {
            int cur = ks & 1, nxt = cur ^ 1;
            if (ks < 3) {
                ldsm4(bf[nxt][0], sB + b_base + 0 * (16 * A_STRIDE) + (ks + 1) * 32);
                ldsm4(bf[nxt][1], sB + b_base + 1 * (16 * A_STRIDE) + (ks + 1) * 32);
            }
            uint32_t a[4][4];
            #pragma unroll
            for (int mi = 0; mi < 4; mi++)
                ldsm4(a[mi], sA + a_base + mi * (16 * A_STRIDE) + ks * 32);
            #pragma unroll
            for (int mi = 0; mi < 4; mi++)
                #pragma unroll
                for (int np = 0; np < 2; np++) {
                    mma16816(c[mi][np * 2 + 0], a[mi], bf[cur][np][0], bf[cur][np][1]);
                    mma16816(c[mi][np * 2 + 1], a[mi], bf[cur][np][2], bf[cur][np][3]);
                }
        }
        if (++stage >= NSTAGE) stage = 0;
    }

    #pragma unroll
    for (int mi = 0; mi < 4; mi++) {
        int r0 = m0 + wm * 64 + mi * 16 + (lane >> 2);
        float f0 = g_feats[r0], f1 = g_feats[r0 + 8];
        #pragma unroll
        for (int ni = 0; ni < 4; ni++) {
            int cc = n0 + wn * 32 + ni * 8 + (lane & 3) * 2;
            float ce0 = g_cents[cc], ce1 = g_cents[cc + 1];
            float* dp = &g_dist2[(size_t)r0 * 4096 + cc];
            float2 v0 = { f0 + ce0 - 2.f * c[mi][ni][0], f0 + ce1 - 2.f * c[mi][ni][1] };
            float2 v1 = { f1 + ce0 - 2.f * c[mi][ni][2], f1 + ce1 - 2.f * c[mi][ni][3] };
            *reinterpret_cast<float2*>(dp) = v0;
            *reinterpret_cast<float2*>(dp + (size_t)8 * 4096) = v1;
        }
    }
}

// ===================== launch 5: top-200 per row =====================
__global__ __launch_bounds__(256) void topk_kernel(float* __restrict__ out) {
    __shared__ unsigned hist[256];
    __shared__ unsigned scan[256];
    __shared__ unsigned sh_want, sh_prefix;
    __shared__ unsigned cnt_lt;
    __shared__ float sel[256];

    int row = blockIdx.x;
    int t = threadIdx.x;
    int lane = t & 31;

    float keys[16];
    const float4* src4 = reinterpret_cast<const float4*>(&g_dist2[(size_t)row * 4096]);
    #pragma unroll
    for (int j = 0; j < 4; j++) {
        float4 v = src4[t + j * 256];
        keys[j * 4 + 0] = v.x; keys[j * 4 + 1] = v.y;
        keys[j * 4 + 2] = v.z; keys[j * 4 + 3] = v.w;
    }
    if (t == 0) { sh_want = NNEI; sh_prefix = 0; cnt_lt = 0; }
    __syncthreads();

    // pass 0: exponent bits cluster -> warp-aggregated atomics
    {
        hist[t] = 0;
        __syncthreads();
        #pragma unroll
        for (int j = 0; j < 16; j++) {
            unsigned d = __float_as_uint(keys[j]) >> 24;
            unsigned m = __match_any_sync(FULLMASK, d);
            if ((m & ((1u << lane) - 1u)) == 0)
                atomicAdd(&hist[d], (unsigned)__popc(m));
        }
        __syncthreads();
        if (t < 32) {
            unsigned vals[8], tot = 0;
            #pragma unroll
            for (int i = 0; i < 8; i++) { vals[i] = hist[t * 8 + i]; tot += vals[i]; }
            unsigned run = tot;
            #pragma unroll
            for (int off = 1; off < 32; off <<= 1) {
                unsigned x = __shfl_up_sync(FULLMASK, run, off);
                if (t >= off) run += x;
            }
            unsigned acc = run - tot;
            #pragma unroll
            for (int i = 0; i < 8; i++) { acc += vals[i]; scan[t * 8 + i] = acc; }
        }
        __syncthreads();
        unsigned below = (t == 0) ? 0u : scan[t - 1];
        if (below < NNEI && NNEI <= scan[t]) {
            sh_want = NNEI - below;
            sh_prefix = (unsigned)t;
        }
        __syncthreads();
    }

    // passes 1-3: plain atomics (bits spread across bins)
    #pragma unroll 1
    for (int pass = 1; pass < 4; pass++) {
        int shift = 24 - pass * 8;
        unsigned pfx = sh_prefix;
        unsigned want = sh_want;
        hist[t] = 0;
        __syncthreads();
        #pragma unroll
        for (int j = 0; j < 16; j++) {
            unsigned u = __float_as_uint(keys[j]);
            if ((u >> (shift + 8)) == pfx)
                atomicAdd(&hist[(u >> shift) & 255u], 1u);
        }
        __syncthreads();
        if (t < 32) {
            unsigned vals[8], tot = 0;
            #pragma unroll
            for (int i = 0; i < 8; i++) { vals[i] = hist[t * 8 + i]; tot += vals[i]; }
            unsigned run = tot;
            #pragma unroll
            for (int off = 1; off < 32; off <<= 1) {
                unsigned x = __shfl_up_sync(FULLMASK, run, off);
                if (t >= off) run += x;
            }
            unsigned acc = run - tot;
            #pragma unroll
            for (int i = 0; i < 8; i++) { acc += vals[i]; scan[t * 8 + i] = acc; }
        }
        __syncthreads();
        unsigned below = (t == 0) ? 0u : scan[t - 1];
        if (below < want && want <= scan[t]) {
            sh_want = want - below;
            sh_prefix = (pfx << 8) | (unsigned)t;
        }
        __syncthreads();
    }

    unsigned Tb = sh_prefix;
    float Tf = __uint_as_float(Tb);
    // warp-aggregated gather of elements < T
    #pragma unroll
    for (int j = 0; j < 16; j++) {
        bool pr = keys[j] < Tf;
        unsigned m = __ballot_sync(FULLMASK, pr);
        if (m) {
            unsigned pos0 = 0;
            if (lane == 0) pos0 = atomicAdd(&cnt_lt, (unsigned)__popc(m));
            pos0 = __shfl_sync(FULLMASK, pos0, 0);
            if (pr) sel[pos0 + __popc(m & ((1u << lane) - 1u))] = keys[j];
        }
    }
    __syncthreads();
    unsigned base = cnt_lt;
    if ((unsigned)t >= base) sel[t] = (t < NNEI) ? Tf : __int_as_float(0x7f800000);
    __syncthreads();

    for (int k = 2; k <= 256; k <<= 1) {
        for (int j = k >> 1; j > 0; j >>= 1) {
            int ixj = t ^ j;
            if (ixj > t) {
                bool up = ((t & k) == 0);
                float a = sel[t], b = sel[ixj];
                if ((a > b) == up) { sel[t] = b; sel[ixj] = a; }
            }
            __syncthreads();
        }
    }

    if (t < NNEI) {
        int b = row >> 12, p = row & 4095;
        out[(((size_t)(b * NNEI + t)) << 12) + p] = sqrtf(sel[t]);
    }
}

// ===================== host launcher =====================
extern "C" void kernel_launch(void* const* d_in, const int* in_sizes, int n_in,
                              void* d_out, int out_size) {
    const float* p0 = (const float*)d_in[0];
    const float* p1 = (const float*)d_in[1];
    const float* p2 = (const float*)d_in[2];
    const float* w1 = (const float*)d_in[5];
    const float* b1 = (const float*)d_in[6];
    const float* w2 = (const float*)d_in[7];
    const float* b2 = (const float*)d_in[8];
    const float* w3 = (const float*)d_in[9];
    const float* b3 = (const float*)d_in[10];
    const float* Cm = (const float*)d_in[11];
    float* score = (float*)d_out;
    float* out2  = score + SCORE_ELEMS;

    static bool attr_set = false;
    if (!attr_set) {
        cudaFuncSetAttribute(gemm_kernel, cudaFuncAttributeMaxDynamicSharedMemorySize, GEMM_SMEM);
        attr_set = true;
    }

    prep_kernel<<<35968, 256>>>(p0, p1, p2, Cm);
    conv_all_kernel<<<1024, 256>>>(w1, b1, w2, b2, w3, b3);
    phi_all_kernel<<<dim3(128, 4), 256>>>(out2);
    gemm_kernel<<<dim3(M_TOT/128, NCENT/128), 256, GEMM_SMEM>>>();
    topk_kernel<<<M_TOT, 256>>>(score);
}

// round 12
// speedup vs baseline: 1.2869x; 1.0066x over previous
#include <cuda_runtime.h>
#include <cuda_bf16.h>
#include <cuda_fp16.h>
#include <cstdint>

#define DI __device__ __forceinline__
#define FULLMASK 0xFFFFFFFFu

// ===================== problem dims =====================
#define NBATCH 4
#define NPIX   4096
#define NCH    1792
#define NCENT  4096
#define M_TOT  (NBATCH*NPIX)
#define NNEI   200
#define SCORE_ELEMS (NBATCH*NNEI*NPIX)
#define DCENTER 1792.0f

// ===================== scratch =====================
__device__ float g_pool0[4u*256*64*64];
__device__ float g_pool1[4u*512*32*32];
__device__ float g_pool2[4u*1024*16*16];
__device__ float g_conv0[4u*256*64*64];
__device__ float g_conv1[4u*512*32*32];
__device__ float g_conv2[4u*1024*16*16];
__device__ __nv_bfloat16 g_phi[(size_t)M_TOT*NCH];
__device__ __nv_bfloat16 g_ct [(size_t)NCENT*NCH];
__device__ float g_feats[M_TOT];
__device__ float g_cents[NCENT];
__device__ __half g_dist2h[(size_t)M_TOT*NCENT];

// ===================== PTX helpers (sm_100 baseline ISA) =====================
DI uint32_t smem_u32(const void* p) {
    uint32_t a;
    asm("{ .reg .u64 t; cvta.to.shared.u64 t, %1; cvt.u32.u64 %0, t; }" : "=r"(a) : "l"(p));
    return a;
}
DI void ldsm4(uint32_t* r, uint32_t a) {
    asm volatile("ldmatrix.sync.aligned.m8n8.x4.shared.b16 {%0,%1,%2,%3}, [%4];"
        : "=r"(r[0]), "=r"(r[1]), "=r"(r[2]), "=r"(r[3]) : "r"(a));
}
DI void mma16816(float* c, const uint32_t* a, uint32_t b0, uint32_t b1) {
    asm volatile("mma.sync.aligned.m16n8k16.row.col.f32.bf16.bf16.f32 "
        "{%0,%1,%2,%3}, {%4,%5,%6,%7}, {%8,%9}, {%0,%1,%2,%3};"
        : "+f"(c[0]), "+f"(c[1]), "+f"(c[2]), "+f"(c[3])
        : "r"(a[0]), "r"(a[1]), "r"(a[2]), "r"(a[3]), "r"(b0), "r"(b1));
}
DI void cpasync16(uint32_t dst, const void* src) {
    asm volatile("cp.async.cg.shared.global [%0], [%1], 16;" :: "r"(dst), "l"(src) : "memory");
}
DI void cp_commit() { asm volatile("cp.async.commit_group;" ::: "memory"); }
DI void cp_wait1()  { asm volatile("cp.async.wait_group 1;" ::: "memory"); }
DI void cp_wait0()  { asm volatile("cp.async.wait_group 0;" ::: "memory"); }

// ===================== launch 1: prep mega-kernel =====================
DI void pool_body(const float* __restrict__ x, float* __restrict__ y,
                  int H, int W, int idx) {
    int w = idx % W;
    int h = (idx / W) % H;
    int bc = idx / (W * H);
    const float* p = x + (size_t)bc * H * W;
    float s = 0.f;
    #pragma unroll
    for (int dy = -1; dy <= 1; dy++) {
        int hh = h + dy;
        if (hh < 0 || hh >= H) continue;
        #pragma unroll
        for (int dx = -1; dx <= 1; dx++) {
            int ww = w + dx;
            if (ww < 0 || ww >= W) continue;
            s += p[hh * W + ww];
        }
    }
    y[idx] = s * (1.0f / 9.0f);
}

__global__ __launch_bounds__(256) void prep_kernel(
    const float* __restrict__ p0, const float* __restrict__ p1,
    const float* __restrict__ p2, const float* __restrict__ C) {
    int bb = blockIdx.x, t = threadIdx.x;
    if (bb < 16384) {
        pool_body(p0, g_pool0, 64, 64, bb * 256 + t);
    } else if (bb < 24576) {
        pool_body(p1, g_pool1, 32, 32, (bb - 16384) * 256 + t);
    } else if (bb < 28672) {
        pool_body(p2, g_pool2, 16, 16, (bb - 24576) * 256 + t);
    } else if (bb < 35840) {
        __shared__ float tile[32][33];
        int id = bb - 28672;
        int j0 = (id & 127) * 32, k0 = (id >> 7) * 32;
        int tx = t & 31, ty = t >> 5;
        for (int i = ty; i < 32; i += 8)
            tile[i][tx] = C[(size_t)(k0 + i) * 4096 + j0 + tx];
        __syncthreads();
        for (int i = ty; i < 32; i += 8)
            g_ct[(size_t)(j0 + i) * NCH + k0 + tx] = __float2bfloat16(tile[tx][i]);
    } else {
        __shared__ float red[256];
        int id = bb - 35840;
        int j = (id & 127) * 32 + (t & 31);
        int kp = t >> 5;
        float s = 0.f;
        int kbeg = kp * 224, kend = kbeg + 224;
        for (int k = kbeg; k < kend; k++) {
            float v = C[(size_t)k * 4096 + j];
            s += v * v;
        }
        red[t] = s;
        __syncthreads();
        if (t < 32) {
            float acc = red[t];
            #pragma unroll
            for (int i = 1; i < 8; i++) acc += red[t + i * 32];
            g_cents[j] = acc;
        }
    }
}

// ===================== launch 2: coord-conv (templated oc tile) =====================
template<int NOC>
DI void conv_body(const float* __restrict__ x, const float* __restrict__ w,
                  const float* __restrict__ bias, float* __restrict__ o,
                  int C, int OC, int H, int W, int b, int px, int ocb,
                  float* Xs, float* Ws, int t) {
    int p0 = px * 64, oc0 = ocb * (NOC * 16);
    int HW = H * W;
    int tx = t & 15, ty = t >> 4;
    int Cp2 = C + 2;
    float acc[NOC][4] = {};
    for (int k0 = 0; k0 < C; k0 += 16) {
        int idx = t;
        #pragma unroll
        for (int i = 0; i < 4; i++, idx += 256) {
            int kk = idx >> 6, pp = idx & 63;
            Xs[kk * 64 + pp] = x[(size_t)(b * C + k0 + kk) * HW + p0 + pp];
        }
        idx = t;
        #pragma unroll
        for (int i = 0; i < NOC; i++, idx += 256) {
            int ocp = idx >> 4, kk = idx & 15;
            Ws[kk * 132 + ocp] = w[(size_t)(oc0 + ocp) * Cp2 + k0 + kk];
        }
        __syncthreads();
        #pragma unroll
        for (int kk = 0; kk < 16; kk++) {
            float4 a4 = *reinterpret_cast<const float4*>(&Xs[kk * 64 + tx * 4]);
            float av[4] = { a4.x, a4.y, a4.z, a4.w };
            float bv[NOC];
            #pragma unroll
            for (int q = 0; q < NOC / 4; q++) {
                float4 b4 = *reinterpret_cast<const float4*>(&Ws[kk * 132 + ty * NOC + q * 4]);
                bv[q * 4 + 0] = b4.x; bv[q * 4 + 1] = b4.y;
                bv[q * 4 + 2] = b4.z; bv[q * 4 + 3] = b4.w;
            }
            #pragma unroll
            for (int i = 0; i < NOC; i++)
                #pragma unroll
                for (int j = 0; j < 4; j++)
                    acc[i][j] += bv[i] * av[j];
        }
        __syncthreads();
    }
    float invW = 2.f / (float)(W - 1), invH = 2.f / (float)(H - 1);
    #pragma unroll
    for (int i = 0; i < NOC; i++) {
        int oc = oc0 + ty * NOC + i;
        float cx = w[(size_t)oc * Cp2 + C];
        float cy = w[(size_t)oc * Cp2 + C + 1];
        float bb = bias[oc];
        #pragma unroll
        for (int j = 0; j < 4; j++) {
            int p = p0 + tx * 4 + j;
            float xg = -1.f + (float)(p % W) * invW;
            float yg = -1.f + (float)(p / W) * invH;
            o[(size_t)(b * OC + oc) * HW + p] = acc[i][j] + cx * xg + cy * yg + bb;
        }
    }
}

__global__ __launch_bounds__(256) void conv_all_kernel(
    const float* __restrict__ w1, const float* __restrict__ b1,
    const float* __restrict__ w2, const float* __restrict__ b2,
    const float* __restrict__ w3, const float* __restrict__ b3) {
    __shared__ float Xs[16 * 64];
    __shared__ float Ws[16 * 132];
    int id = blockIdx.x, t = threadIdx.x;
    if (id < 256) {
        int b = id >> 6, rem = id & 63;
        conv_body<4>(g_pool2, w3, b3, g_conv2, 1024, 1024, 16, 16,
                     b, rem & 3, rem >> 2, Xs, Ws, t);
    } else if (id < 512) {
        int v = id - 256;
        int b = v >> 6, rem = v & 63;
        conv_body<8>(g_pool1, w2, b2, g_conv1, 512, 512, 32, 32,
                     b, rem & 15, rem >> 4, Xs, Ws, t);
    } else {
        int v = id - 512;
        int b = v >> 7, rem = v & 127;
        conv_body<8>(g_pool0, w1, b1, g_conv0, 256, 256, 64, 64,
                     b, rem & 63, rem >> 6, Xs, Ws, t);
    }
}

// ===================== launch 3: phi (fused resize + out2 + feats) =====================
DI float bilin(const float* __restrict__ sp, int S, int p) {
    int h = p >> 6, ww = p & 63;
    float sc = (float)S / 64.f;
    float fy = ((float)h + 0.5f) * sc - 0.5f; fy = fminf(fmaxf(fy, 0.f), (float)(S - 1));
    float fx = ((float)ww + 0.5f) * sc - 0.5f; fx = fminf(fmaxf(fx, 0.f), (float)(S - 1));
    int y0 = (int)fy, x0 = (int)fx;
    int y1 = min(y0 + 1, S - 1), x1 = min(x0 + 1, S - 1);
    float wy = fy - (float)y0, wx = fx - (float)x0;
    float v00 = sp[y0 * S + x0], v01 = sp[y0 * S + x1];
    float v10 = sp[y1 * S + x0], v11 = sp[y1 * S + x1];
    return (1.f - wy) * ((1.f - wx) * v00 + wx * v01) + wy * ((1.f - wx) * v10 + wx * v11);
}

DI float fetch2(int b, int ch, int p) {
    if (ch < 256)  return g_conv0[(((size_t)(b * 256 + ch)) << 12) + p];
    if (ch < 768)  return bilin(&g_conv1[(size_t)(b * 512 + ch - 256) * 1024], 32, p);
    return bilin(&g_conv2[(size_t)(b * 1024 + ch - 768) * 256], 16, p);
}

__global__ __launch_bounds__(256) void phi_all_kernel(float* __restrict__ out2) {
    __shared__ float tile[32][33];
    __shared__ float fsmem[32];
    int b = blockIdx.y, p0 = blockIdx.x * 32;
    int tx = threadIdx.x & 31, ty = threadIdx.x >> 5;
    if (threadIdx.x < 32) fsmem[threadIdx.x] = 0.f;
    __syncthreads();
    #pragma unroll 1
    for (int ch0 = 0; ch0 < NCH; ch0 += 32) {
        for (int i = ty; i < 32; i += 8) {
            int ch = ch0 + i, p = p0 + tx;
            float v = fetch2(b, ch, p);
            tile[i][tx] = v;
            if (ch < 896)
                out2[(((size_t)(b * 896 + ch)) << 12) + p] = v;
        }
        __syncthreads();
        for (int i = ty; i < 32; i += 8) {
            int p = p0 + i;
            float v = tile[tx][i];
            g_phi[(size_t)(b * 4096 + p) * NCH + ch0 + tx] = __float2bfloat16(v);
            float s = v * v;
            s += __shfl_xor_sync(FULLMASK, s, 16);
            s += __shfl_xor_sync(FULLMASK, s, 8);
            s += __shfl_xor_sync(FULLMASK, s, 4);
            s += __shfl_xor_sync(FULLMASK, s, 2);
            s += __shfl_xor_sync(FULLMASK, s, 1);
            if (tx == 0) fsmem[i] += s;
        }
        __syncthreads();
    }
    if (threadIdx.x < 32)
        g_feats[b * 4096 + p0 + threadIdx.x] = fsmem[threadIdx.x];
}

// ===================== launch 4: distance GEMM (R7/R9 optimum config) =====================
#define A_STRIDE 144
#define SA_BYTES (128*144)
#define STAGE_BYTES (2*SA_BYTES)
#define NSTAGE 3
#define GEMM_SMEM (NSTAGE*STAGE_BYTES)    // 110592
#define NKCHUNK 28

DI void gemm_load_chunk(uint32_t sbuf, int m0, int n0, int k0, int t) {
    uint32_t sA = sbuf, sB = sbuf + SA_BYTES;
    #pragma unroll
    for (int i = 0; i < 4; i++) {
        int idx = t + i * 256;
        int row = idx >> 3, seg = idx & 7;
        cpasync16(sA + row * A_STRIDE + seg * 16,
                  &g_phi[(size_t)(m0 + row) * NCH + k0 + seg * 8]);
    }
    #pragma unroll
    for (int i = 0; i < 4; i++) {
        int idx = t + i * 256;
        int row = idx >> 3, seg = idx & 7;
        cpasync16(sB + row * A_STRIDE + seg * 16,
                  &g_ct[(size_t)(n0 + row) * NCH + k0 + seg * 8]);
    }
    cp_commit();
}

__global__ __launch_bounds__(256, 2) void gemm_kernel() {
    extern __shared__ __align__(16) char smem[];
    const uint32_t sbase = smem_u32(smem);
    int t = threadIdx.x, lane = t & 31, wid = t >> 5;
    int wm = wid & 1, wn = wid >> 1;     // 2 x 4 warp grid; warp tile 64x32
    int m0 = blockIdx.x * 128, n0 = blockIdx.y * 128;

    float c[4][4][4];
    #pragma unroll
    for (int i = 0; i < 4; i++)
        #pragma unroll
        for (int j = 0; j < 4; j++)
            #pragma unroll
            for (int r = 0; r < 4; r++) c[i][j][r] = 0.f;

    const uint32_t a_row = wm * 64 + (lane & 15);
    const uint32_t a_base = a_row * A_STRIDE + ((lane >> 4) * 16);
    const uint32_t b_row = wn * 32 + ((lane >> 4) * 8) + (lane & 7);
    const uint32_t b_base = b_row * A_STRIDE + (((lane >> 3) & 1) * 16);

    gemm_load_chunk(sbase, m0, n0, 0, t);
    gemm_load_chunk(sbase + STAGE_BYTES, m0, n0, 64, t);

    int stage = 0;
    #pragma unroll 1
    for (int ck = 0; ck < NKCHUNK; ck++) {
        if (ck == NKCHUNK - 1) cp_wait0(); else cp_wait1();
        __syncthreads();
        if (ck + 2 < NKCHUNK) {
            int ls = stage + 2; if (ls >= NSTAGE) ls -= NSTAGE;
            gemm_load_chunk(sbase + ls * STAGE_BYTES, m0, n0, (ck + 2) * 64, t);
        }
        uint32_t sA = sbase + stage * STAGE_BYTES;
        uint32_t sB = sA + SA_BYTES;
        #pragma unroll
        for (int ks = 0; ks < 4; ks++) {
            uint32_t a[4][4];
            #pragma unroll
            for (int mi = 0; mi < 4; mi++)
                ldsm4(a[mi], sA + a_base + mi * (16 * A_STRIDE) + ks * 32);
            uint32_t bfr[2][4];
            #pragma unroll
            for (int np = 0; np < 2; np++)
                ldsm4(bfr[np], sB + b_base + np * (16 * A_STRIDE) + ks * 32);
            #pragma unroll
            for (int mi = 0; mi < 4; mi++)
                #pragma unroll
                for (int np = 0; np < 2; np++) {
                    mma16816(c[mi][np * 2 + 0], a[mi], bfr[np][0], bfr[np][1]);
                    mma16816(c[mi][np * 2 + 1], a[mi], bfr[np][2], bfr[np][3]);
                }
        }
        if (++stage >= NSTAGE) stage = 0;
    }

    // epilogue: store centered fp16 dist2 (dist2 - DCENTER)
    #pragma unroll
    for (int mi = 0; mi < 4; mi++) {
        int r0 = m0 + wm * 64 + mi * 16 + (lane >> 2);
        float f0 = g_feats[r0] - DCENTER, f1 = g_feats[r0 + 8] - DCENTER;
        #pragma unroll
        for (int ni = 0; ni < 4; ni++) {
            int cc = n0 + wn * 32 + ni * 8 + (lane & 3) * 2;
            float ce0 = g_cents[cc], ce1 = g_cents[cc + 1];
            __half* dp = &g_dist2h[(size_t)r0 * 4096 + cc];
            __half2 h0 = __floats2half2_rn(f0 + ce0 - 2.f * c[mi][ni][0],
                                           f0 + ce1 - 2.f * c[mi][ni][1]);
            __half2 h1 = __floats2half2_rn(f1 + ce0 - 2.f * c[mi][ni][2],
                                           f1 + ce1 - 2.f * c[mi][ni][3]);
            *reinterpret_cast<__half2*>(dp) = h0;
            *reinterpret_cast<__half2*>(dp + (size_t)8 * 4096) = h1;
        }
    }
}

// ===================== launch 5: top-200 per row (fp16 keys) =====================
__global__ __launch_bounds__(256) void topk_kernel(float* __restrict__ out) {
    __shared__ unsigned hist[256];
    __shared__ unsigned scan[256];
    __shared__ unsigned sh_want, sh_prefix;
    __shared__ unsigned cnt_lt;
    __shared__ float sel[256];

    int row = blockIdx.x;
    int t = threadIdx.x;
    int lane = t & 31;

    // 16 keys per thread: 2 x uint4 = 2 x 8 halves, coalesced
    float keys[16];
    const uint4* src = reinterpret_cast<const uint4*>(&g_dist2h[(size_t)row * 4096]);
    #pragma unroll
    for (int j = 0; j < 2; j++) {
        uint4 v = src[t + j * 256];
        unsigned ws[4] = { v.x, v.y, v.z, v.w };
        #pragma unroll
        for (int q = 0; q < 4; q++) {
            __half2 hh = *reinterpret_cast<__half2*>(&ws[q]);
            float2 f = __half22float2(hh);
            keys[j * 8 + q * 2 + 0] = f.x + DCENTER;
            keys[j * 8 + q * 2 + 1] = f.y + DCENTER;
        }
    }
    if (t == 0) { sh_want = NNEI; sh_prefix = 0; cnt_lt = 0; }
    __syncthreads();

    // pass 0: exponent bits cluster -> warp-aggregated atomics
    {
        hist[t] = 0;
        __syncthreads();
        #pragma unroll
        for (int j = 0; j < 16; j++) {
            unsigned d = __float_as_uint(keys[j]) >> 24;
            unsigned m = __match_any_sync(FULLMASK, d);
            if ((m & ((1u << lane) - 1u)) == 0)
                atomicAdd(&hist[d], (unsigned)__popc(m));
        }
        __syncthreads();
        if (t < 32) {
            unsigned vals[8], tot = 0;
            #pragma unroll
            for (int i = 0; i < 8; i++) { vals[i] = hist[t * 8 + i]; tot += vals[i]; }
            unsigned run = tot;
            #pragma unroll
            for (int off = 1; off < 32; off <<= 1) {
                unsigned x = __shfl_up_sync(FULLMASK, run, off);
                if (t >= off) run += x;
            }
            unsigned acc = run - tot;
            #pragma unroll
            for (int i = 0; i < 8; i++) { acc += vals[i]; scan[t * 8 + i] = acc; }
        }
        __syncthreads();
        unsigned below = (t == 0) ? 0u : scan[t - 1];
        if (below < NNEI && NNEI <= scan[t]) {
            sh_want = NNEI - below;
            sh_prefix = (unsigned)t;
        }
        __syncthreads();
    }

    // passes 1-3: plain atomics
    #pragma unroll 1
    for (int pass = 1; pass < 4; pass++) {
        int shift = 24 - pass * 8;
        unsigned pfx = sh_prefix;
        unsigned want = sh_want;
        hist[t] = 0;
        __syncthreads();
        #pragma unroll
        for (int j = 0; j < 16; j++) {
            unsigned u = __float_as_uint(keys[j]);
            if ((u >> (shift + 8)) == pfx)
                atomicAdd(&hist[(u >> shift) & 255u], 1u);
        }
        __syncthreads();
        if (t < 32) {
            unsigned vals[8], tot = 0;
            #pragma unroll
            for (int i = 0; i < 8; i++) { vals[i] = hist[t * 8 + i]; tot += vals[i]; }
            unsigned run = tot;
            #pragma unroll
            for (int off = 1; off < 32; off <<= 1) {
                unsigned x = __shfl_up_sync(FULLMASK, run, off);
                if (t >= off) run += x;
            }
            unsigned acc = run - tot;
            #pragma unroll
            for (int i = 0; i < 8; i++) { acc += vals[i]; scan[t * 8 + i] = acc; }
        }
        __syncthreads();
        unsigned below = (t == 0) ? 0u : scan[t - 1];
        if (below < want && want <= scan[t]) {
            sh_want = want - below;
            sh_prefix = (pfx << 8) | (unsigned)t;
        }
        __syncthreads();
    }

    unsigned Tb = sh_prefix;
    float Tf = __uint_as_float(Tb);
    // warp-aggregated gather of elements < T
    #pragma unroll
    for (int j = 0; j < 16; j++) {
        bool pr = keys[j] < Tf;
        unsigned m = __ballot_sync(FULLMASK, pr);
        if (m) {
            unsigned pos0 = 0;
            if (lane == 0) pos0 = atomicAdd(&cnt_lt, (unsigned)__popc(m));
            pos0 = __shfl_sync(FULLMASK, pos0, 0);
            if (pr) sel[pos0 + __popc(m & ((1u << lane) - 1u))] = keys[j];
        }
    }
    __syncthreads();
    unsigned base = cnt_lt;
    if ((unsigned)t >= base) sel[t] = (t < NNEI) ? Tf : __int_as_float(0x7f800000);
    __syncthreads();

    for (int k = 2; k <= 256; k <<= 1) {
        for (int j = k >> 1; j > 0; j >>= 1) {
            int ixj = t ^ j;
            if (ixj > t) {
                bool up = ((t & k) == 0);
                float a = sel[t], b = sel[ixj];
                if ((a > b) == up) { sel[t] = b; sel[ixj] = a; }
            }
            __syncthreads();
        }
    }

    if (t < NNEI) {
        int b = row >> 12, p = row & 4095;
        out[(((size_t)(b * NNEI + t)) << 12) + p] = sqrtf(sel[t]);
    }
}

// ===================== host launcher =====================
extern "C" void kernel_launch(void* const* d_in, const int* in_sizes, int n_in,
                              void* d_out, int out_size) {
    const float* p0 = (const float*)d_in[0];
    const float* p1 = (const float*)d_in[1];
    const float* p2 = (const float*)d_in[2];
    const float* w1 = (const float*)d_in[5];
    const float* b1 = (const float*)d_in[6];
    const float* w2 = (const float*)d_in[7];
    const float* b2 = (const float*)d_in[8];
    const float* w3 = (const float*)d_in[9];
    const float* b3 = (const float*)d_in[10];
    const float* Cm = (const float*)d_in[11];
    float* score = (float*)d_out;
    float* out2  = score + SCORE_ELEMS;

    static bool attr_set = false;
    if (!attr_set) {
        cudaFuncSetAttribute(gemm_kernel, cudaFuncAttributeMaxDynamicSharedMemorySize, GEMM_SMEM);
        attr_set = true;
    }

    prep_kernel<<<35968, 256>>>(p0, p1, p2, Cm);
    conv_all_kernel<<<1024, 256>>>(w1, b1, w2, b2, w3, b3);
    phi_all_kernel<<<dim3(128, 4), 256>>>(out2);
    gemm_kernel<<<dim3(M_TOT/128, NCENT/128), 256, GEMM_SMEM>>>();
    topk_kernel<<<M_TOT, 256>>>(score);
}

// round 13
// speedup vs baseline: 1.3651x; 1.0608x over previous
#include <cuda_runtime.h>
#include <cuda_bf16.h>
#include <cuda_fp16.h>
#include <cstdint>

#define DI __device__ __forceinline__
#define FULLMASK 0xFFFFFFFFu

// ===================== problem dims =====================
#define NBATCH 4
#define NPIX   4096
#define NCH    1792
#define NCENT  4096
#define M_TOT  (NBATCH*NPIX)
#define NNEI   200
#define SCORE_ELEMS (NBATCH*NNEI*NPIX)
#define DCENTER 1792.0f

// ===================== scratch =====================
// split-bf16 transposed pooled inputs: x' = [xh | xl | xh], row-major [b*HW+p][3C]
__device__ __nv_bfloat16 g_xp0[(size_t)4*4096*768];
__device__ __nv_bfloat16 g_xp1[(size_t)4*1024*1536];
__device__ __nv_bfloat16 g_xp2[(size_t)4*256*3072];
// split-bf16 weights: w' = [wh | wh | wl], row-major [oc][3C]
__device__ __nv_bfloat16 g_wp1[(size_t)256*768];
__device__ __nv_bfloat16 g_wp2[(size_t)512*1536];
__device__ __nv_bfloat16 g_wp3[(size_t)1024*3072];
__device__ float g_conv0[4u*256*64*64];
__device__ float g_conv1[4u*512*32*32];
__device__ float g_conv2[4u*1024*16*16];
__device__ __nv_bfloat16 g_phi[(size_t)M_TOT*NCH];
__device__ __nv_bfloat16 g_ct [(size_t)NCENT*NCH];
__device__ float g_feats[M_TOT];
__device__ float g_cents[NCENT];
__device__ __half g_dist2h[(size_t)M_TOT*NCENT];

// ===================== PTX helpers (sm_100 baseline ISA) =====================
DI uint32_t smem_u32(const void* p) {
    uint32_t a;
    asm("{ .reg .u64 t; cvta.to.shared.u64 t, %1; cvt.u32.u64 %0, t; }" : "=r"(a) : "l"(p));
    return a;
}
DI void ldsm4(uint32_t* r, uint32_t a) {
    asm volatile("ldmatrix.sync.aligned.m8n8.x4.shared.b16 {%0,%1,%2,%3}, [%4];"
        : "=r"(r[0]), "=r"(r[1]), "=r"(r[2]), "=r"(r[3]) : "r"(a));
}
DI void mma16816(float* c, const uint32_t* a, uint32_t b0, uint32_t b1) {
    asm volatile("mma.sync.aligned.m16n8k16.row.col.f32.bf16.bf16.f32 "
        "{%0,%1,%2,%3}, {%4,%5,%6,%7}, {%8,%9}, {%0,%1,%2,%3};"
        : "+f"(c[0]), "+f"(c[1]), "+f"(c[2]), "+f"(c[3])
        : "r"(a[0]), "r"(a[1]), "r"(a[2]), "r"(a[3]), "r"(b0), "r"(b1));
}
DI void cpasync16(uint32_t dst, const void* src) {
    asm volatile("cp.async.cg.shared.global [%0], [%1], 16;" :: "r"(dst), "l"(src) : "memory");
}
DI void cp_commit() { asm volatile("cp.async.commit_group;" ::: "memory"); }
DI void cp_wait1()  { asm volatile("cp.async.wait_group 1;" ::: "memory"); }
DI void cp_wait0()  { asm volatile("cp.async.wait_group 0;" ::: "memory"); }

// ===================== launch 1: prep mega-kernel =====================
// blocks: [0,7168) poolT (pool+transpose+split) | [7168,14336) C-transpose |
//         [14336,14464) cents | [14464,16256) w' split conversion
DI float pool_val(const float* __restrict__ plane, int H, int W, int p) {
    int w = p % W, h = p / W;
    float s = 0.f;
    #pragma unroll
    for (int dy = -1; dy <= 1; dy++) {
        int hh = h + dy;
        if (hh < 0 || hh >= H) continue;
        #pragma unroll
        for (int dx = -1; dx <= 1; dx++) {
            int ww = w + dx;
            if (ww < 0 || ww >= W) continue;
            s += plane[hh * W + ww];
        }
    }
    return s * (1.0f / 9.0f);
}

DI void poolT_body(const float* __restrict__ x, __nv_bfloat16* __restrict__ xp,
                   int C, int H, int W, int b, int ct, int ht,
                   float (*tile)[33], int t) {
    int c0 = ct * 32, hw0 = ht * 32;
    int HW = H * W, K3 = 3 * C;
    int tx = t & 31, ty = t >> 5;
    for (int i = ty; i < 32; i += 8) {
        int c = c0 + i;
        tile[i][tx] = pool_val(x + (size_t)(b * C + c) * HW, H, W, hw0 + tx);
    }
    __syncthreads();
    for (int i = ty; i < 32; i += 8) {
        int p = hw0 + i;
        float v = tile[tx][i];
        __nv_bfloat16 hi = __float2bfloat16(v);
        __nv_bfloat16 lo = __float2bfloat16(v - __bfloat162float(hi));
        size_t rb = (size_t)(b * HW + p) * K3;
        xp[rb + c0 + tx] = hi;
        xp[rb + C + c0 + tx] = lo;
        xp[rb + 2 * C + c0 + tx] = hi;
    }
    __syncthreads();
}

__global__ __launch_bounds__(256) void prep_kernel(
    const float* __restrict__ p0, const float* __restrict__ p1,
    const float* __restrict__ p2, const float* __restrict__ C,
    const float* __restrict__ w1, const float* __restrict__ w2,
    const float* __restrict__ w3) {
    __shared__ float tile[32][33];
    int bb = blockIdx.x, t = threadIdx.x;
    if (bb < 7168) {
        if (bb < 4096) {            // L0: 8 ct x 128 ht x 4 b
            int b = bb >> 10, rem = bb & 1023;
            poolT_body(p0, g_xp0, 256, 64, 64, b, rem >> 7, rem & 127, tile, t);
        } else if (bb < 6144) {     // L1: 16 ct x 32 ht x 4 b
            int v = bb - 4096;
            int b = v >> 9, rem = v & 511;
            poolT_body(p1, g_xp1, 512, 32, 32, b, rem >> 5, rem & 31, tile, t);
        } else {                    // L2: 32 ct x 8 ht x 4 b
            int v = bb - 6144;
            int b = v >> 8, rem = v & 255;
            poolT_body(p2, g_xp2, 1024, 16, 16, b, rem >> 3, rem & 7, tile, t);
        }
    } else if (bb < 14336) {
        int id = bb - 7168;
        int j0 = (id & 127) * 32, k0 = (id >> 7) * 32;
        int tx = t & 31, ty = t >> 5;
        for (int i = ty; i < 32; i += 8)
            tile[i][tx] = C[(size_t)(k0 + i) * 4096 + j0 + tx];
        __syncthreads();
        for (int i = ty; i < 32; i += 8)
            g_ct[(size_t)(j0 + i) * NCH + k0 + tx] = __float2bfloat16(tile[tx][i]);
    } else if (bb < 14464) {
        __shared__ float red[256];
        int id = bb - 14336;
        int j = (id & 127) * 32 + (t & 31);
        int kp = t >> 5;
        float s = 0.f;
        int kbeg = kp * 224, kend = kbeg + 224;
        for (int k = kbeg; k < kend; k++) {
            float v = C[(size_t)k * 4096 + j];
            s += v * v;
        }
        red[t] = s;
        __syncthreads();
        if (t < 32) {
            float acc = red[t];
            #pragma unroll
            for (int i = 1; i < 8; i++) acc += red[t + i * 32];
            g_cents[j] = acc;
        }
    } else {
        // w' conversion: one block per oc row
        int id = bb - 14464;
        const float* wsrc; __nv_bfloat16* wdst; int Cc, oc;
        if (id < 256)      { wsrc = w1; wdst = g_wp1; Cc = 256;  oc = id; }
        else if (id < 768) { wsrc = w2; wdst = g_wp2; Cc = 512;  oc = id - 256; }
        else               { wsrc = w3; wdst = g_wp3; Cc = 1024; oc = id - 768; }
        int K3 = 3 * Cc, Cp2 = Cc + 2;
        for (int c = t; c < Cc; c += 256) {
            float v = wsrc[(size_t)oc * Cp2 + c];
            __nv_bfloat16 hi = __float2bfloat16(v);
            __nv_bfloat16 lo = __float2bfloat16(v - __bfloat162float(hi));
            wdst[(size_t)oc * K3 + c] = hi;
            wdst[(size_t)oc * K3 + Cc + c] = hi;
            wdst[(size_t)oc * K3 + 2 * Cc + c] = lo;
        }
    }
}

// NOTE on w'/x' segment pairing: w' = [wh|wh|wl], x' = [xh|xl|xh]
// => dot = wh.xh + wh.xl + wl.xh  (missing wl.xl ~ 4e-6 rel)

// ===================== shared GEMM tile constants =====================
#define A_STRIDE 144
#define SA_BYTES (128*144)
#define STAGE_BYTES (2*SA_BYTES)
#define NSTAGE 3
#define GEMM_SMEM (NSTAGE*STAGE_BYTES)    // 110592

DI void tile_load_chunk(uint32_t sbuf, const __nv_bfloat16* __restrict__ aptr,
                        const __nv_bfloat16* __restrict__ bptr,
                        int Kst, int k0, int t) {
    uint32_t sA = sbuf, sB = sbuf + SA_BYTES;
    #pragma unroll
    for (int i = 0; i < 4; i++) {
        int idx = t + i * 256;
        int row = idx >> 3, seg = idx & 7;
        cpasync16(sA + row * A_STRIDE + seg * 16, aptr + (size_t)row * Kst + k0 + seg * 8);
    }
    #pragma unroll
    for (int i = 0; i < 4; i++) {
        int idx = t + i * 256;
        int row = idx >> 3, seg = idx & 7;
        cpasync16(sB + row * A_STRIDE + seg * 16, bptr + (size_t)row * Kst + k0 + seg * 8);
    }
    cp_commit();
}

// core 128x128 mainloop: accumulates into c[4][4][4]
DI void tile_mainloop(uint32_t sbase, const __nv_bfloat16* aptr, const __nv_bfloat16* bptr,
                      int Kst, int nchunk, int t, uint32_t a_base, uint32_t b_base,
                      float c[4][4][4]) {
    tile_load_chunk(sbase, aptr, bptr, Kst, 0, t);
    tile_load_chunk(sbase + STAGE_BYTES, aptr, bptr, Kst, 64, t);
    int stage = 0;
    #pragma unroll 1
    for (int ck = 0; ck < nchunk; ck++) {
        if (ck == nchunk - 1) cp_wait0(); else cp_wait1();
        __syncthreads();
        if (ck + 2 < nchunk) {
            int ls = stage + 2; if (ls >= NSTAGE) ls -= NSTAGE;
            tile_load_chunk(sbase + ls * STAGE_BYTES, aptr, bptr, Kst, (ck + 2) * 64, t);
        }
        uint32_t sA = sbase + stage * STAGE_BYTES;
        uint32_t sB = sA + SA_BYTES;
        #pragma unroll
        for (int ks = 0; ks < 4; ks++) {
            uint32_t a[4][4];
            #pragma unroll
            for (int mi = 0; mi < 4; mi++)
                ldsm4(a[mi], sA + a_base + mi * (16 * A_STRIDE) + ks * 32);
            uint32_t bfr[2][4];
            #pragma unroll
            for (int np = 0; np < 2; np++)
                ldsm4(bfr[np], sB + b_base + np * (16 * A_STRIDE) + ks * 32);
            #pragma unroll
            for (int mi = 0; mi < 4; mi++)
                #pragma unroll
                for (int np = 0; np < 2; np++) {
                    mma16816(c[mi][np * 2 + 0], a[mi], bfr[np][0], bfr[np][1]);
                    mma16816(c[mi][np * 2 + 1], a[mi], bfr[np][2], bfr[np][3]);
                }
        }
        if (++stage >= NSTAGE) stage = 0;
    }
}

// ===================== launch 2: conv via split-bf16 tensor GEMM =====================
// grid 448: [0,64) L2 | [64,192) L1 | [192,448) L0
__global__ __launch_bounds__(256, 2) void convmma_kernel(
    const float* __restrict__ w1, const float* __restrict__ b1,
    const float* __restrict__ w2, const float* __restrict__ b2,
    const float* __restrict__ w3, const float* __restrict__ b3) {
    extern __shared__ __align__(16) char smem[];
    const uint32_t sbase = smem_u32(smem);
    int id = blockIdx.x, t = threadIdx.x, lane = t & 31, wid = t >> 5;
    int wm = wid & 1, wn = wid >> 1;

    const __nv_bfloat16 *wp, *xp;
    float* o; const float *wsrc, *bsrc;
    int OC, HW, W, H, Cc, b, oc0, pp0;
    if (id < 64) {
        b = id >> 4; int rem = id & 15; oc0 = (rem >> 1) * 128; pp0 = (rem & 1) * 128;
        wp = g_wp3; xp = g_xp2; o = g_conv2; wsrc = w3; bsrc = b3;
        OC = 1024; HW = 256; W = 16; H = 16; Cc = 1024;
    } else if (id < 192) {
        int v = id - 64; b = v >> 5; int rem = v & 31; oc0 = (rem >> 3) * 128; pp0 = (rem & 7) * 128;
        wp = g_wp2; xp = g_xp1; o = g_conv1; wsrc = w2; bsrc = b2;
        OC = 512; HW = 1024; W = 32; H = 32; Cc = 512;
    } else {
        int v = id - 192; b = v >> 6; int rem = v & 63; oc0 = (rem >> 5) * 128; pp0 = (rem & 31) * 128;
        wp = g_wp1; xp = g_xp0; o = g_conv0; wsrc = w1; bsrc = b1;
        OC = 256; HW = 4096; W = 64; H = 64; Cc = 256;
    }
    int K3 = 3 * Cc, nchunk = K3 / 64, Cp2 = Cc + 2;

    float c[4][4][4];
    #pragma unroll
    for (int i = 0; i < 4; i++)
        #pragma unroll
        for (int j = 0; j < 4; j++)
            #pragma unroll
            for (int r = 0; r < 4; r++) c[i][j][r] = 0.f;

    const uint32_t a_row = wm * 64 + (lane & 15);
    const uint32_t a_base = a_row * A_STRIDE + ((lane >> 4) * 16);
    const uint32_t b_row = wn * 32 + ((lane >> 4) * 8) + (lane & 7);
    const uint32_t b_base = b_row * A_STRIDE + (((lane >> 3) & 1) * 16);

    const __nv_bfloat16* aptr = wp + (size_t)oc0 * K3;
    const __nv_bfloat16* bptr = xp + (size_t)(b * HW + pp0) * K3;
    tile_mainloop(sbase, aptr, bptr, K3, nchunk, t, a_base, b_base, c);

    float invW = 2.f / (float)(W - 1), invH = 2.f / (float)(H - 1);
    #pragma unroll
    for (int mi = 0; mi < 4; mi++) {
        int r0 = oc0 + wm * 64 + mi * 16 + (lane >> 2);
        int r1 = r0 + 8;
        float cx0 = wsrc[(size_t)r0 * Cp2 + Cc], cy0 = wsrc[(size_t)r0 * Cp2 + Cc + 1], bb0 = bsrc[r0];
        float cx1 = wsrc[(size_t)r1 * Cp2 + Cc], cy1 = wsrc[(size_t)r1 * Cp2 + Cc + 1], bb1 = bsrc[r1];
        #pragma unroll
        for (int ni = 0; ni < 4; ni++) {
            int cc = pp0 + wn * 32 + ni * 8 + (lane & 3) * 2;
            float xga = -1.f + (float)(cc % W) * invW, yga = -1.f + (float)(cc / W) * invH;
            float xgb = -1.f + (float)((cc + 1) % W) * invW, ygb = -1.f + (float)((cc + 1) / W) * invH;
            float2 v0 = { c[mi][ni][0] + cx0 * xga + cy0 * yga + bb0,
                          c[mi][ni][1] + cx0 * xgb + cy0 * ygb + bb0 };
            float2 v1 = { c[mi][ni][2] + cx1 * xga + cy1 * yga + bb1,
                          c[mi][ni][3] + cx1 * xgb + cy1 * ygb + bb1 };
            *reinterpret_cast<float2*>(&o[(size_t)(b * OC + r0) * HW + cc]) = v0;
            *reinterpret_cast<float2*>(&o[(size_t)(b * OC + r1) * HW + cc]) = v1;
        }
    }
}

// ===================== launch 3: phi (fused resize + out2 + feats) =====================
DI float bilin(const float* __restrict__ sp, int S, int p) {
    int h = p >> 6, ww = p & 63;
    float sc = (float)S / 64.f;
    float fy = ((float)h + 0.5f) * sc - 0.5f; fy = fminf(fmaxf(fy, 0.f), (float)(S - 1));
    float fx = ((float)ww + 0.5f) * sc - 0.5f; fx = fminf(fmaxf(fx, 0.f), (float)(S - 1));
    int y0 = (int)fy, x0 = (int)fx;
    int y1 = min(y0 + 1, S - 1), x1 = min(x0 + 1, S - 1);
    float wy = fy - (float)y0, wx = fx - (float)x0;
    float v00 = sp[y0 * S + x0], v01 = sp[y0 * S + x1];
    float v10 = sp[y1 * S + x0], v11 = sp[y1 * S + x1];
    return (1.f - wy) * ((1.f - wx) * v00 + wx * v01) + wy * ((1.f - wx) * v10 + wx * v11);
}

DI float fetch2(int b, int ch, int p) {
    if (ch < 256)  return g_conv0[(((size_t)(b * 256 + ch)) << 12) + p];
    if (ch < 768)  return bilin(&g_conv1[(size_t)(b * 512 + ch - 256) * 1024], 32, p);
    return bilin(&g_conv2[(size_t)(b * 1024 + ch - 768) * 256], 16, p);
}

__global__ __launch_bounds__(256) void phi_all_kernel(float* __restrict__ out2) {
    __shared__ float tile[32][33];
    __shared__ float fsmem[32];
    int b = blockIdx.y, p0 = blockIdx.x * 32;
    int tx = threadIdx.x & 31, ty = threadIdx.x >> 5;
    if (threadIdx.x < 32) fsmem[threadIdx.x] = 0.f;
    __syncthreads();
    #pragma unroll 1
    for (int ch0 = 0; ch0 < NCH; ch0 += 32) {
        for (int i = ty; i < 32; i += 8) {
            int ch = ch0 + i, p = p0 + tx;
            float v = fetch2(b, ch, p);
            tile[i][tx] = v;
            if (ch < 896)
                out2[(((size_t)(b * 896 + ch)) << 12) + p] = v;
        }
        __syncthreads();
        for (int i = ty; i < 32; i += 8) {
            int p = p0 + i;
            float v = tile[tx][i];
            g_phi[(size_t)(b * 4096 + p) * NCH + ch0 + tx] = __float2bfloat16(v);
            float s = v * v;
            s += __shfl_xor_sync(FULLMASK, s, 16);
            s += __shfl_xor_sync(FULLMASK, s, 8);
            s += __shfl_xor_sync(FULLMASK, s, 4);
            s += __shfl_xor_sync(FULLMASK, s, 2);
            s += __shfl_xor_sync(FULLMASK, s, 1);
            if (tx == 0) fsmem[i] += s;
        }
        __syncthreads();
    }
    if (threadIdx.x < 32)
        g_feats[b * 4096 + p0 + threadIdx.x] = fsmem[threadIdx.x];
}

// ===================== launch 4: distance GEMM (R7/R9 optimum) =====================
__global__ __launch_bounds__(256, 2) void gemm_kernel() {
    extern __shared__ __align__(16) char smem[];
    const uint32_t sbase = smem_u32(smem);
    int t = threadIdx.x, lane = t & 31, wid = t >> 5;
    int wm = wid & 1, wn = wid >> 1;
    int m0 = blockIdx.x * 128, n0 = blockIdx.y * 128;

    float c[4][4][4];
    #pragma unroll
    for (int i = 0; i < 4; i++)
        #pragma unroll
        for (int j = 0; j < 4; j++)
            #pragma unroll
            for (int r = 0; r < 4; r++) c[i][j][r] = 0.f;

    const uint32_t a_row = wm * 64 + (lane & 15);
    const uint32_t a_base = a_row * A_STRIDE + ((lane >> 4) * 16);
    const uint32_t b_row = wn * 32 + ((lane >> 4) * 8) + (lane & 7);
    const uint32_t b_base = b_row * A_STRIDE + (((lane >> 3) & 1) * 16);

    tile_mainloop(sbase, &g_phi[(size_t)m0 * NCH], &g_ct[(size_t)n0 * NCH],
                  NCH, NCH / 64, t, a_base, b_base, c);

    #pragma unroll
    for (int mi = 0; mi < 4; mi++) {
        int r0 = m0 + wm * 64 + mi * 16 + (lane >> 2);
        float f0 = g_feats[r0] - DCENTER, f1 = g_feats[r0 + 8] - DCENTER;
        #pragma unroll
        for (int ni = 0; ni < 4; ni++) {
            int cc = n0 + wn * 32 + ni * 8 + (lane & 3) * 2;
            float ce0 = g_cents[cc], ce1 = g_cents[cc + 1];
            __half* dp = &g_dist2h[(size_t)r0 * 4096 + cc];
            __half2 h0 = __floats2half2_rn(f0 + ce0 - 2.f * c[mi][ni][0],
                                           f0 + ce1 - 2.f * c[mi][ni][1]);
            __half2 h1 = __floats2half2_rn(f1 + ce0 - 2.f * c[mi][ni][2],
                                           f1 + ce1 - 2.f * c[mi][ni][3]);
            *reinterpret_cast<__half2*>(dp) = h0;
            *reinterpret_cast<__half2*>(dp + (size_t)8 * 4096) = h1;
        }
    }
}

// ===================== launch 5: top-200 per row (16-bit keys, 2 radix passes) =====================
DI unsigned order16(unsigned h) {   // order-isomorphic uint16 of fp16 bits
    return (h & 0x8000u) ? ((~h) & 0xFFFFu) : (h | 0x8000u);
}

__global__ __launch_bounds__(256) void topk_kernel(float* __restrict__ out) {
    __shared__ unsigned hist[256];
    __shared__ unsigned scan[256];
    __shared__ unsigned sh_want, sh_prefix;
    __shared__ unsigned cnt_lt;
    __shared__ int sel[256];

    int row = blockIdx.x;
    int t = threadIdx.x;
    int lane = t & 31;

    unsigned keys[16];
    const uint4* src = reinterpret_cast<const uint4*>(&g_dist2h[(size_t)row * 4096]);
    #pragma unroll
    for (int j = 0; j < 2; j++) {
        uint4 v = src[t + j * 256];
        unsigned ws[4] = { v.x, v.y, v.z, v.w };
        #pragma unroll
        for (int q = 0; q < 4; q++) {
            keys[j * 8 + q * 2 + 0] = order16(ws[q] & 0xFFFFu);
            keys[j * 8 + q * 2 + 1] = order16(ws[q] >> 16);
        }
    }
    if (t == 0) { sh_want = NNEI; sh_prefix = 0; cnt_lt = 0; }
    __syncthreads();

    // pass 0: high byte (clustered) -> warp-aggregated atomics
    {
        hist[t] = 0;
        __syncthreads();
        #pragma unroll
        for (int j = 0; j < 16; j++) {
            unsigned d = keys[j] >> 8;
            unsigned m = __match_any_sync(FULLMASK, d);
            if ((m & ((1u << lane) - 1u)) == 0)
                atomicAdd(&hist[d], (unsigned)__popc(m));
        }
        __syncthreads();
        if (t < 32) {
            unsigned vals[8], tot = 0;
            #pragma unroll
            for (int i = 0; i < 8; i++) { vals[i] = hist[t * 8 + i]; tot += vals[i]; }
            unsigned run = tot;
            #pragma unroll
            for (int off = 1; off < 32; off <<= 1) {
                unsigned x = __shfl_up_sync(FULLMASK, run, off);
                if (t >= off) run += x;
            }
            unsigned acc = run - tot;
            #pragma unroll
            for (int i = 0; i < 8; i++) { acc += vals[i]; scan[t * 8 + i] = acc; }
        }
        __syncthreads();
        unsigned below = (t == 0) ? 0u : scan[t - 1];
        if (below < NNEI && NNEI <= scan[t]) {
            sh_want = NNEI - below;
            sh_prefix = (unsigned)t;
        }
        __syncthreads();
    }

    // pass 1: low byte, plain atomics
    {
        unsigned pfx = sh_prefix;
        unsigned want = sh_want;
        hist[t] = 0;
        __syncthreads();
        #pragma unroll
        for (int j = 0; j < 16; j++) {
            unsigned u = keys[j];
            if ((u >> 8) == pfx)
                atomicAdd(&hist[u & 255u], 1u);
        }
        __syncthreads();
        if (t < 32) {
            unsigned vals[8], tot = 0;
            #pragma unroll
            for (int i = 0; i < 8; i++) { vals[i] = hist[t * 8 + i]; tot += vals[i]; }
            unsigned run = tot;
            #pragma unroll
            for (int off = 1; off < 32; off <<= 1) {
                unsigned x = __shfl_up_sync(FULLMASK, run, off);
                if (t >= off) run += x;
            }
            unsigned acc = run - tot;
            #pragma unroll
            for (int i = 0; i < 8; i++) { acc += vals[i]; scan[t * 8 + i] = acc; }
        }
        __syncthreads();
        unsigned below = (t == 0) ? 0u : scan[t - 1];
        if (below < want && want <= scan[t]) {
            sh_prefix = (pfx << 8) | (unsigned)t;
        }
        __syncthreads();
    }

    unsigned T = sh_prefix;   // exact 16-bit threshold key
    // warp-aggregated gather of keys < T
    #pragma unroll
    for (int j = 0; j < 16; j++) {
        bool pr = keys[j] < T;
        unsigned m = __ballot_sync(FULLMASK, pr);
        if (m) {
            unsigned pos0 = 0;
            if (lane == 0) pos0 = atomicAdd(&cnt_lt, (unsigned)__popc(m));
            pos0 = __shfl_sync(FULLMASK, pos0, 0);
            if (pr) sel[pos0 + __popc(m & ((1u << lane) - 1u))] = (int)keys[j];
        }
    }
    __syncthreads();
    unsigned base = cnt_lt;
    if ((unsigned)t >= base) sel[t] = (t < NNEI) ? (int)T : 0x7FFFFFFF;
    __syncthreads();

    // bitonic sort 256 ints ascending
    for (int k = 2; k <= 256; k <<= 1) {
        for (int j = k >> 1; j > 0; j >>= 1) {
            int ixj = t ^ j;
            if (ixj > t) {
                bool up = ((t & k) == 0);
                int a = sel[t], bv = sel[ixj];
                if ((a > bv) == up) { sel[t] = bv; sel[ixj] = a; }
            }
            __syncthreads();
        }
    }

    if (t < NNEI) {
        unsigned u = (unsigned)sel[t];
        unsigned h = (u & 0x8000u) ? (u & 0x7FFFu) : ((~u) & 0xFFFFu);
        float f = __half2float(__ushort_as_half((unsigned short)h)) + DCENTER;
        int b = row >> 12, p = row & 4095;
        out[(((size_t)(b * NNEI + t)) << 12) + p] = sqrtf(f);
    }
}

// ===================== host launcher =====================
extern "C" void kernel_launch(void* const* d_in, const int* in_sizes, int n_in,
                              void* d_out, int out_size) {
    const float* p0 = (const float*)d_in[0];
    const float* p1 = (const float*)d_in[1];
    const float* p2 = (const float*)d_in[2];
    const float* w1 = (const float*)d_in[5];
    const float* b1 = (const float*)d_in[6];
    const float* w2 = (const float*)d_in[7];
    const float* b2 = (const float*)d_in[8];
    const float* w3 = (const float*)d_in[9];
    const float* b3 = (const float*)d_in[10];
    const float* Cm = (const float*)d_in[11];
    float* score = (float*)d_out;
    float* out2  = score + SCORE_ELEMS;

    static bool attr_set = false;
    if (!attr_set) {
        cudaFuncSetAttribute(gemm_kernel, cudaFuncAttributeMaxDynamicSharedMemorySize, GEMM_SMEM);
        cudaFuncSetAttribute(convmma_kernel, cudaFuncAttributeMaxDynamicSharedMemorySize, GEMM_SMEM);
        attr_set = true;
    }

    prep_kernel<<<16256, 256>>>(p0, p1, p2, Cm, w1, w2, w3);
    convmma_kernel<<<448, 256, GEMM_SMEM>>>(w1, b1, w2, b2, w3, b3);
    phi_all_kernel<<<dim3(128, 4), 256>>>(out2);
    gemm_kernel<<<dim3(M_TOT/128, NCENT/128), 256, GEMM_SMEM>>>();
    topk_kernel<<<M_TOT, 256>>>(score);
}